// round 8
// baseline (speedup 1.0000x reference)
#include <cuda_runtime.h>
#include <cuda_bf16.h>
#include <cuda_fp16.h>
#include <cstdint>

// Problem constants (fixed by the dataset)
#define NN   100000      // nodes
#define EE   1600000     // edges
#define CAP  128         // adjacency bucket capacity per node
#define NSM  152         // GB300 SM count

// ---------------- scratch (device globals; no allocation allowed) ----------
__device__ __half         g_h0[(size_t)NN * 128];   // x @ W1 (fp16)
__device__ __nv_bfloat16  g_h1hi[(size_t)NN * 128]; // relu(agg h0), bf16 hi
__device__ __nv_bfloat16  g_h1lo[(size_t)NN * 128]; // bf16 lo plane
__device__ __half         g_h2[(size_t)NN * 64];    // h1 @ W2 (fp16)
__device__ int            g_deg[NN];
__device__ int            g_adj[(size_t)NN * CAP];
__device__ __nv_bfloat16  g_w1hi[128 * 128], g_w1lo[128 * 128];
__device__ __nv_bfloat16  g_w2hi[64 * 128],  g_w2lo[64 * 128];

#define ROWB 272   // smem row pitch: 128 bf16 (256B) + 16B pad, ldmatrix conflict-free

// ---------------- prep 1: clear degrees + W1 hi/lo transpose ----------------
__global__ void k_prep_w1(const float* __restrict__ W1,
                          __nv_bfloat16* __restrict__ w1hi, __nv_bfloat16* __restrict__ w1lo) {
    int i = blockIdx.x * blockDim.x + threadIdx.x;
    if (i < NN) g_deg[i] = 0;
    if (i < 128 * 128) {
        int k = i / 128, n = i % 128;
        float w = W1[i];
        __nv_bfloat16 h = __float2bfloat16_rn(w);
        w1hi[n * 128 + k] = h;
        w1lo[n * 128 + k] = __float2bfloat16_rn(w - __bfloat162float(h));
    }
}

// ---------------- prep 2: W2 hi/lo transpose --------------------------------
__global__ void k_prep_w2(const float* __restrict__ W2,
                          __nv_bfloat16* __restrict__ w2hi, __nv_bfloat16* __restrict__ w2lo) {
    int i = blockIdx.x * blockDim.x + threadIdx.x;
    if (i < 128 * 64) {
        int k = i / 64, n = i % 64;
        float w = W2[i];
        __nv_bfloat16 h = __float2bfloat16_rn(w);
        w2hi[n * 128 + k] = h;
        w2lo[n * 128 + k] = __float2bfloat16_rn(w - __bfloat162float(h));
    }
}

// ---------------- adjacency build: 4 edges/thread ---------------------------
__global__ void k_build_adj(const int* __restrict__ erow,
                            const int* __restrict__ ecol) {
    int e0 = (blockIdx.x * blockDim.x + threadIdx.x) * 4;
    if (e0 >= EE) return;
    int4 r = *reinterpret_cast<const int4*>(erow + e0);
    int4 c = *reinterpret_cast<const int4*>(ecol + e0);
    int p0 = atomicAdd(&g_deg[r.x], 1);
    int p1 = atomicAdd(&g_deg[r.y], 1);
    int p2 = atomicAdd(&g_deg[r.z], 1);
    int p3 = atomicAdd(&g_deg[r.w], 1);
    if (p0 < CAP) g_adj[(size_t)r.x * CAP + p0] = c.x;
    if (p1 < CAP) g_adj[(size_t)r.y * CAP + p1] = c.y;
    if (p2 < CAP) g_adj[(size_t)r.z * CAP + p2] = c.z;
    if (p3 < CAP) g_adj[(size_t)r.w * CAP + p3] = c.w;
}

// ---------------- mma / ldmatrix helpers -------------------------------------
#define LDMX4(r0, r1, r2, r3, addr) \
    asm volatile("ldmatrix.sync.aligned.m8n8.x4.shared.b16 {%0,%1,%2,%3}, [%4];" \
                 : "=r"(r0), "=r"(r1), "=r"(r2), "=r"(r3) : "r"(addr))
#define LDMX2(r0, r1, addr) \
    asm volatile("ldmatrix.sync.aligned.m8n8.x2.shared.b16 {%0,%1}, [%2];" \
                 : "=r"(r0), "=r"(r1) : "r"(addr))
#define MMA_BF16(acc, a, b0, b1) \
    asm volatile("mma.sync.aligned.m16n8k16.row.col.f32.bf16.bf16.f32 " \
                 "{%0,%1,%2,%3}, {%4,%5,%6,%7}, {%8,%9}, {%0,%1,%2,%3};" \
                 : "+f"(acc[0]), "+f"(acc[1]), "+f"(acc[2]), "+f"(acc[3]) \
                 : "r"(a[0]), "r"(a[1]), "r"(a[2]), "r"(a[3]), "r"(b0), "r"(b1))

// ---------------- GEMM1: fp32 A -> bf16 hi/lo split, N-split CTAs ------------
// Output C[nrows,128](fp16). Each CTA computes a 64-row x 64-col tile:
// n-half = blockIdx.x & 1. 8 warps = 2M x 4N, warp tile 32x16 (NT=2).
__global__ __launch_bounds__(256, 3)
void k_gemm_conv(const float* __restrict__ A,
                 const __nv_bfloat16* __restrict__ Bhi, const __nv_bfloat16* __restrict__ Blo,
                 __half* __restrict__ C, int nrows) {
    constexpr int NC = 64;           // columns per CTA
    constexpr int WN = 16, NT = 2;
    constexpr int B_BYTES = NC * ROWB;
    constexpr int A_BYTES = 64 * ROWB;

    extern __shared__ char smem[];
    char* sBhi = smem;
    char* sBlo = smem + B_BYTES;
    char* sAhi = sBlo + B_BYTES;
    char* sAlo = sAhi + A_BYTES;

    const int nh = blockIdx.x & 1;              // which 64-col half
    const int cta = blockIdx.x >> 1;
    const int nctas = gridDim.x >> 1;

    const int tid = threadIdx.x;
    const int lane = tid & 31;
    const int wid = tid >> 5;
    const int g = lane >> 2;
    const int tg = lane & 3;
    const int mbase = (wid & 1) * 32;
    const int nbase = (wid >> 1) * WN;

    const __nv_bfloat16* Bh = Bhi + nh * 64 * 128;
    const __nv_bfloat16* Bl = Blo + nh * 64 * 128;

    // stage B hi/lo once (64 rows x 16 uint4)
    for (int i = tid; i < NC * 16; i += 256) {
        int n = i >> 4, q = i & 15;
        *reinterpret_cast<uint4*>(sBhi + n * ROWB + q * 16) =
            reinterpret_cast<const uint4*>(Bh + n * 128)[q];
        *reinterpret_cast<uint4*>(sBlo + n * ROWB + q * 16) =
            reinterpret_cast<const uint4*>(Bl + n * 128)[q];
    }

    // ldmatrix base addresses
    const int rlm = lane & 7;
    const int qa = lane >> 3;
    uint32_t aAhi[2], aAlo[2];
#pragma unroll
    for (int mt = 0; mt < 2; mt++) {
        int row = mbase + mt * 16 + (qa & 1) * 8 + rlm;
        int col = (qa >> 1) * 16;
        aAhi[mt] = (uint32_t)__cvta_generic_to_shared(sAhi) + row * ROWB + col;
        aAlo[mt] = (uint32_t)__cvta_generic_to_shared(sAlo) + row * ROWB + col;
    }
    const int lb = lane & 15;
    uint32_t aBhi[NT], aBlo[NT];
#pragma unroll
    for (int nt = 0; nt < NT; nt++) {
        int row = nbase + nt * 8 + (lb & 7);
        int col = ((lb >> 3) & 1) * 16;
        aBhi[nt] = (uint32_t)__cvta_generic_to_shared(sBhi) + row * ROWB + col;
        aBlo[nt] = (uint32_t)__cvta_generic_to_shared(sBlo) + row * ROWB + col;
    }

    const int ntiles = (nrows + 63) / 64;
    for (int t = cta; t < ntiles; t += nctas) {
        const int r0 = t * 64;
        __syncthreads();

        // stage A tile: front-batch loads (MLP), then convert fp32 -> bf16 hi/lo
        // 64 rows x 32 float4 chunks = 2048; 8 per thread
        float4 v[8];
        const int m0 = tid >> 5;           // rows m0, m0+8, ..., m0+56
        const int q0 = tid & 31;           // float4 column
#pragma unroll
        for (int it = 0; it < 8; it++) {
            int gr = r0 + m0 + it * 8;
            v[it] = (gr < nrows)
                ? *reinterpret_cast<const float4*>(A + (size_t)gr * 128 + q0 * 4)
                : make_float4(0.f, 0.f, 0.f, 0.f);
        }
#pragma unroll
        for (int it = 0; it < 8; it++) {
            int m = m0 + it * 8;
            __nv_bfloat162 h01 = __float22bfloat162_rn(make_float2(v[it].x, v[it].y));
            __nv_bfloat162 h23 = __float22bfloat162_rn(make_float2(v[it].z, v[it].w));
            float2 f01 = __bfloat1622float2(h01);
            float2 f23 = __bfloat1622float2(h23);
            __nv_bfloat162 l01 = __float22bfloat162_rn(make_float2(v[it].x - f01.x, v[it].y - f01.y));
            __nv_bfloat162 l23 = __float22bfloat162_rn(make_float2(v[it].z - f23.x, v[it].w - f23.y));
            *reinterpret_cast<uint2*>(sAhi + m * ROWB + q0 * 8) = make_uint2(
                *reinterpret_cast<uint32_t*>(&h01), *reinterpret_cast<uint32_t*>(&h23));
            *reinterpret_cast<uint2*>(sAlo + m * ROWB + q0 * 8) = make_uint2(
                *reinterpret_cast<uint32_t*>(&l01), *reinterpret_cast<uint32_t*>(&l23));
        }
        __syncthreads();

        float acc[2][NT][4];
#pragma unroll
        for (int mt = 0; mt < 2; mt++)
#pragma unroll
            for (int nt = 0; nt < NT; nt++)
#pragma unroll
                for (int j = 0; j < 4; j++) acc[mt][nt][j] = 0.0f;

#pragma unroll
        for (int ks = 0; ks < 8; ks++) {
            const uint32_t ko = ks * 32;
            uint32_t ah[2][4], al[2][4];
#pragma unroll
            for (int mt = 0; mt < 2; mt++) {
                LDMX4(ah[mt][0], ah[mt][1], ah[mt][2], ah[mt][3], aAhi[mt] + ko);
                LDMX4(al[mt][0], al[mt][1], al[mt][2], al[mt][3], aAlo[mt] + ko);
            }
#pragma unroll
            for (int nt = 0; nt < NT; nt++) {
                uint32_t bh0, bh1, bl0, bl1;
                LDMX2(bh0, bh1, aBhi[nt] + ko);
                LDMX2(bl0, bl1, aBlo[nt] + ko);
#pragma unroll
                for (int mt = 0; mt < 2; mt++) {
                    MMA_BF16(acc[mt][nt], ah[mt], bh0, bh1);
                    MMA_BF16(acc[mt][nt], ah[mt], bl0, bl1);
                    MMA_BF16(acc[mt][nt], al[mt], bh0, bh1);
                }
            }
        }

        // epilogue: fp16 out; row stride 128, column offset nh*64
#pragma unroll
        for (int mt = 0; mt < 2; mt++) {
#pragma unroll
            for (int nt = 0; nt < NT; nt++) {
                int r1 = r0 + mbase + mt * 16 + g;
                int r2 = r1 + 8;
                int cc = nh * 64 + nbase + nt * 8 + tg * 2;
                if (r1 < nrows)
                    *reinterpret_cast<__half2*>(C + (size_t)r1 * 128 + cc) =
                        __floats2half2_rn(acc[mt][nt][0], acc[mt][nt][1]);
                if (r2 < nrows)
                    *reinterpret_cast<__half2*>(C + (size_t)r2 * 128 + cc) =
                        __floats2half2_rn(acc[mt][nt][2], acc[mt][nt][3]);
            }
        }
    }
}

// ---------------- GEMM2: pre-split bf16 A planes -----------------------------
// C[nrows,64](fp16) = A[nrows,128](bf16 hi/lo) @ W2. 8 warps = 2M x 4N.
__global__ __launch_bounds__(256, 3)
void k_gemm_pre(const __nv_bfloat16* __restrict__ Ahi, const __nv_bfloat16* __restrict__ Alo,
                const __nv_bfloat16* __restrict__ Bhi, const __nv_bfloat16* __restrict__ Blo,
                __half* __restrict__ C, int nrows) {
    constexpr int NCOL = 64;
    constexpr int WN = 16, NT = 2;
    constexpr int B_BYTES = NCOL * ROWB;
    constexpr int A_BYTES = 64 * ROWB;

    extern __shared__ char smem[];
    char* sBhi = smem;
    char* sBlo = smem + B_BYTES;
    char* sAhi = sBlo + B_BYTES;
    char* sAlo = sAhi + A_BYTES;

    const int tid = threadIdx.x;
    const int lane = tid & 31;
    const int wid = tid >> 5;
    const int g = lane >> 2;
    const int tg = lane & 3;
    const int mbase = (wid & 1) * 32;
    const int nbase = (wid >> 1) * WN;

    for (int i = tid; i < NCOL * 16; i += 256) {
        int n = i >> 4, q = i & 15;
        *reinterpret_cast<uint4*>(sBhi + n * ROWB + q * 16) =
            reinterpret_cast<const uint4*>(Bhi + n * 128)[q];
        *reinterpret_cast<uint4*>(sBlo + n * ROWB + q * 16) =
            reinterpret_cast<const uint4*>(Blo + n * 128)[q];
    }

    const int rlm = lane & 7;
    const int qa = lane >> 3;
    uint32_t aAhi[2], aAlo[2];
#pragma unroll
    for (int mt = 0; mt < 2; mt++) {
        int row = mbase + mt * 16 + (qa & 1) * 8 + rlm;
        int col = (qa >> 1) * 16;
        aAhi[mt] = (uint32_t)__cvta_generic_to_shared(sAhi) + row * ROWB + col;
        aAlo[mt] = (uint32_t)__cvta_generic_to_shared(sAlo) + row * ROWB + col;
    }
    const int lb = lane & 15;
    uint32_t aBhi[NT], aBlo[NT];
#pragma unroll
    for (int nt = 0; nt < NT; nt++) {
        int row = nbase + nt * 8 + (lb & 7);
        int col = ((lb >> 3) & 1) * 16;
        aBhi[nt] = (uint32_t)__cvta_generic_to_shared(sBhi) + row * ROWB + col;
        aBlo[nt] = (uint32_t)__cvta_generic_to_shared(sBlo) + row * ROWB + col;
    }

    const int ntiles = (nrows + 63) / 64;
    for (int t = blockIdx.x; t < ntiles; t += gridDim.x) {
        const int r0 = t * 64;
        __syncthreads();

        // stage A tile: straight uint4 copies, front-batched
        uint4 v[8];
        const int half = tid >> 7;          // 0: hi plane, 1: lo plane (128 thr each)
        const int m0 = (tid & 127) >> 4;    // rows m0, m0+8, ..
        const int q0 = tid & 15;
        const __nv_bfloat16* Ap = half ? Alo : Ahi;
        char* sp = half ? sAlo : sAhi;
#pragma unroll
        for (int it = 0; it < 8; it++) {
            int gr = r0 + m0 + it * 8;
            v[it] = (gr < nrows)
                ? reinterpret_cast<const uint4*>(Ap + (size_t)gr * 128)[q0]
                : make_uint4(0u, 0u, 0u, 0u);
        }
#pragma unroll
        for (int it = 0; it < 8; it++)
            *reinterpret_cast<uint4*>(sp + (m0 + it * 8) * ROWB + q0 * 16) = v[it];
        __syncthreads();

        float acc[2][NT][4];
#pragma unroll
        for (int mt = 0; mt < 2; mt++)
#pragma unroll
            for (int nt = 0; nt < NT; nt++)
#pragma unroll
                for (int j = 0; j < 4; j++) acc[mt][nt][j] = 0.0f;

#pragma unroll
        for (int ks = 0; ks < 8; ks++) {
            const uint32_t ko = ks * 32;
            uint32_t ah[2][4], al[2][4];
#pragma unroll
            for (int mt = 0; mt < 2; mt++) {
                LDMX4(ah[mt][0], ah[mt][1], ah[mt][2], ah[mt][3], aAhi[mt] + ko);
                LDMX4(al[mt][0], al[mt][1], al[mt][2], al[mt][3], aAlo[mt] + ko);
            }
#pragma unroll
            for (int nt = 0; nt < NT; nt++) {
                uint32_t bh0, bh1, bl0, bl1;
                LDMX2(bh0, bh1, aBhi[nt] + ko);
                LDMX2(bl0, bl1, aBlo[nt] + ko);
#pragma unroll
                for (int mt = 0; mt < 2; mt++) {
                    MMA_BF16(acc[mt][nt], ah[mt], bh0, bh1);
                    MMA_BF16(acc[mt][nt], ah[mt], bl0, bl1);
                    MMA_BF16(acc[mt][nt], al[mt], bh0, bh1);
                }
            }
        }

#pragma unroll
        for (int mt = 0; mt < 2; mt++) {
#pragma unroll
            for (int nt = 0; nt < NT; nt++) {
                int r1 = r0 + mbase + mt * 16 + g;
                int r2 = r1 + 8;
                int cc = nbase + nt * 8 + tg * 2;
                if (r1 < nrows)
                    *reinterpret_cast<__half2*>(C + (size_t)r1 * NCOL + cc) =
                        __floats2half2_rn(acc[mt][nt][0], acc[mt][nt][1]);
                if (r2 < nrows)
                    *reinterpret_cast<__half2*>(C + (size_t)r2 * NCOL + cc) =
                        __floats2half2_rn(acc[mt][nt][2], acc[mt][nt][3]);
            }
        }
    }
}

// ---------------- agg1: mean + relu, fp16 in -> bf16 hi/lo out ---------------
__global__ void k_agg1(const __half* __restrict__ src,
                       __nv_bfloat16* __restrict__ dhi, __nv_bfloat16* __restrict__ dlo) {
    const int gw = (blockIdx.x * blockDim.x + threadIdx.x) >> 5;
    if (gw >= NN) return;
    const int lane = threadIdx.x & 31;

    const int d = g_deg[gw];
    const int cnt = d < CAP ? d : CAP;
    const int* __restrict__ adj = g_adj + (size_t)gw * CAP;

    float acc[4] = {0.f, 0.f, 0.f, 0.f};
#pragma unroll 4
    for (int t = 0; t < cnt; t++) {
        int j = __ldg(&adj[t]);
        uint2 v = *reinterpret_cast<const uint2*>(src + (size_t)j * 128 + lane * 4);
        float2 f0 = __half22float2(*reinterpret_cast<__half2*>(&v.x));
        float2 f1 = __half22float2(*reinterpret_cast<__half2*>(&v.y));
        acc[0] += f0.x; acc[1] += f0.y; acc[2] += f1.x; acc[3] += f1.y;
    }

    const float inv = 1.0f / (float)d;
    float o0 = fmaxf(acc[0] * inv, 0.f), o1 = fmaxf(acc[1] * inv, 0.f);
    float o2 = fmaxf(acc[2] * inv, 0.f), o3 = fmaxf(acc[3] * inv, 0.f);

    __nv_bfloat162 h01 = __float22bfloat162_rn(make_float2(o0, o1));
    __nv_bfloat162 h23 = __float22bfloat162_rn(make_float2(o2, o3));
    float2 f01 = __bfloat1622float2(h01);
    float2 f23 = __bfloat1622float2(h23);
    __nv_bfloat162 l01 = __float22bfloat162_rn(make_float2(o0 - f01.x, o1 - f01.y));
    __nv_bfloat162 l23 = __float22bfloat162_rn(make_float2(o2 - f23.x, o3 - f23.y));

    size_t off = (size_t)gw * 128 + lane * 4;
    *reinterpret_cast<uint2*>(dhi + off) = make_uint2(
        *reinterpret_cast<uint32_t*>(&h01), *reinterpret_cast<uint32_t*>(&h23));
    *reinterpret_cast<uint2*>(dlo + off) = make_uint2(
        *reinterpret_cast<uint32_t*>(&l01), *reinterpret_cast<uint32_t*>(&l23));
}

// ---------------- agg2: mean, fp16 in -> fp32 out -----------------------------
__global__ void k_agg2(const __half* __restrict__ src, float* __restrict__ dst) {
    const int gw = (blockIdx.x * blockDim.x + threadIdx.x) >> 5;
    if (gw >= NN) return;
    const int lane = threadIdx.x & 31;

    const int d = g_deg[gw];
    const int cnt = d < CAP ? d : CAP;
    const int* __restrict__ adj = g_adj + (size_t)gw * CAP;

    float acc0 = 0.f, acc1 = 0.f;
#pragma unroll 4
    for (int t = 0; t < cnt; t++) {
        int j = __ldg(&adj[t]);
        uint32_t v = *reinterpret_cast<const uint32_t*>(src + (size_t)j * 64 + lane * 2);
        float2 f = __half22float2(*reinterpret_cast<__half2*>(&v));
        acc0 += f.x; acc1 += f.y;
    }
    const float inv = 1.0f / (float)d;
    *reinterpret_cast<float2*>(dst + (size_t)gw * 64 + lane * 2) =
        make_float2(acc0 * inv, acc1 * inv);
}

// ---------------- launch --------------------------------------------------------
extern "C" void kernel_launch(void* const* d_in, const int* in_sizes, int n_in,
                              void* d_out, int out_size) {
    const float* x    = (const float*)d_in[0];
    const float* W1   = (const float*)d_in[1];
    const float* W2   = (const float*)d_in[2];
    const int*   erow = (const int*)d_in[3];
    const int*   ecol = (const int*)d_in[4];
    float* out = (float*)d_out;

    __half *h0, *h2;
    __nv_bfloat16 *h1hi, *h1lo, *w1hi, *w1lo, *w2hi, *w2lo;
    cudaGetSymbolAddress((void**)&h0,   g_h0);
    cudaGetSymbolAddress((void**)&h1hi, g_h1hi);
    cudaGetSymbolAddress((void**)&h1lo, g_h1lo);
    cudaGetSymbolAddress((void**)&h2,   g_h2);
    cudaGetSymbolAddress((void**)&w1hi, g_w1hi);
    cudaGetSymbolAddress((void**)&w1lo, g_w1lo);
    cudaGetSymbolAddress((void**)&w2hi, g_w2hi);
    cudaGetSymbolAddress((void**)&w2lo, g_w2lo);

    const int SMEM = 2 * 64 * ROWB + 2 * 64 * ROWB;   // 69632 -> 3 CTA/SM
    cudaFuncSetAttribute(k_gemm_conv, cudaFuncAttributeMaxDynamicSharedMemorySize, SMEM);
    cudaFuncSetAttribute(k_gemm_pre,  cudaFuncAttributeMaxDynamicSharedMemorySize, SMEM);

    // launch order puts gemm1 in profiler slot #4
    k_prep_w1<<<(NN + 255) / 256, 256>>>(W1, w1hi, w1lo);                         // 1
    k_prep_w2<<<(128 * 64 + 255) / 256, 256>>>(W2, w2hi, w2lo);                   // 2
    k_build_adj<<<(EE / 4 + 255) / 256, 256>>>(erow, ecol);                       // 3
    k_gemm_conv<<<6 * NSM, 256, SMEM>>>(x, w1hi, w1lo, h0, NN);                   // 4
    k_agg1<<<(NN * 32 + 255) / 256, 256>>>(h0, h1hi, h1lo);                       // 5
    k_gemm_pre<<<3 * NSM, 256, SMEM>>>(h1hi, h1lo, w2hi, w2lo, h2, NN);           // 6
    k_agg2<<<(NN * 32 + 255) / 256, 256>>>(h2, out);                              // 7
}

// round 9
// speedup vs baseline: 1.0741x; 1.0741x over previous
#include <cuda_runtime.h>
#include <cuda_bf16.h>
#include <cuda_fp16.h>
#include <cstdint>

// Problem constants (fixed by the dataset)
#define NN   100000      // nodes
#define EE   1600000     // edges
#define CAP  128         // adjacency bucket capacity per node
#define NSM  152         // GB300 SM count

// ---------------- scratch (device globals; no allocation allowed) ----------
__device__ __half         g_h0[(size_t)NN * 128];   // x @ W1 (fp16)
__device__ __nv_bfloat16  g_h1hi[(size_t)NN * 128]; // relu(agg h0), bf16 hi
__device__ __nv_bfloat16  g_h1lo[(size_t)NN * 128]; // bf16 lo plane
__device__ __half         g_h2[(size_t)NN * 64];    // h1 @ W2 (fp16)
__device__ int            g_deg[NN];
__device__ int            g_adj[(size_t)NN * CAP];
__device__ __nv_bfloat16  g_w1hi[128 * 128], g_w1lo[128 * 128];
__device__ __nv_bfloat16  g_w2hi[64 * 128],  g_w2lo[64 * 128];

#define ROWB 272   // smem row pitch: 128 bf16 (256B) + 16B pad, ldmatrix conflict-free

// ---------------- prep 1: clear degrees + W1 hi/lo transpose ----------------
__global__ void k_prep_w1(const float* __restrict__ W1,
                          __nv_bfloat16* __restrict__ w1hi, __nv_bfloat16* __restrict__ w1lo) {
    int i = blockIdx.x * blockDim.x + threadIdx.x;
    if (i < NN) g_deg[i] = 0;
    if (i < 128 * 128) {
        int k = i / 128, n = i % 128;
        float w = W1[i];
        __nv_bfloat16 h = __float2bfloat16_rn(w);
        w1hi[n * 128 + k] = h;
        w1lo[n * 128 + k] = __float2bfloat16_rn(w - __bfloat162float(h));
    }
}

// ---------------- prep 2: W2 hi/lo transpose --------------------------------
__global__ void k_prep_w2(const float* __restrict__ W2,
                          __nv_bfloat16* __restrict__ w2hi, __nv_bfloat16* __restrict__ w2lo) {
    int i = blockIdx.x * blockDim.x + threadIdx.x;
    if (i < 128 * 64) {
        int k = i / 64, n = i % 64;
        float w = W2[i];
        __nv_bfloat16 h = __float2bfloat16_rn(w);
        w2hi[n * 128 + k] = h;
        w2lo[n * 128 + k] = __float2bfloat16_rn(w - __bfloat162float(h));
    }
}

// ---------------- adjacency build: 4 edges/thread ---------------------------
__global__ void k_build_adj(const int* __restrict__ erow,
                            const int* __restrict__ ecol) {
    int e0 = (blockIdx.x * blockDim.x + threadIdx.x) * 4;
    if (e0 >= EE) return;
    int4 r = *reinterpret_cast<const int4*>(erow + e0);
    int4 c = *reinterpret_cast<const int4*>(ecol + e0);
    int p0 = atomicAdd(&g_deg[r.x], 1);
    int p1 = atomicAdd(&g_deg[r.y], 1);
    int p2 = atomicAdd(&g_deg[r.z], 1);
    int p3 = atomicAdd(&g_deg[r.w], 1);
    if (p0 < CAP) g_adj[(size_t)r.x * CAP + p0] = c.x;
    if (p1 < CAP) g_adj[(size_t)r.y * CAP + p1] = c.y;
    if (p2 < CAP) g_adj[(size_t)r.z * CAP + p2] = c.z;
    if (p3 < CAP) g_adj[(size_t)r.w * CAP + p3] = c.w;
}

// ---------------- mma / ldmatrix helpers -------------------------------------
#define LDMX4(r0, r1, r2, r3, addr) \
    asm volatile("ldmatrix.sync.aligned.m8n8.x4.shared.b16 {%0,%1,%2,%3}, [%4];" \
                 : "=r"(r0), "=r"(r1), "=r"(r2), "=r"(r3) : "r"(addr))
#define LDMX2(r0, r1, addr) \
    asm volatile("ldmatrix.sync.aligned.m8n8.x2.shared.b16 {%0,%1}, [%2];" \
                 : "=r"(r0), "=r"(r1) : "r"(addr))
#define MMA_BF16(acc, a, b0, b1) \
    asm volatile("mma.sync.aligned.m16n8k16.row.col.f32.bf16.bf16.f32 " \
                 "{%0,%1,%2,%3}, {%4,%5,%6,%7}, {%8,%9}, {%0,%1,%2,%3};" \
                 : "+f"(acc[0]), "+f"(acc[1]), "+f"(acc[2]), "+f"(acc[3]) \
                 : "r"(a[0]), "r"(a[1]), "r"(a[2]), "r"(a[3]), "r"(b0), "r"(b1))

// ---------------- GEMM1: fp32 A -> bf16 hi/lo, register-prefetch pipeline ----
// Output C[nrows,128](fp16). CTA tile 64 rows x 64 cols (nh = blockIdx.x & 1).
// Loop: [STS convert v] sync [LDG next tile into v] [MMA + epilogue] sync.
__global__ __launch_bounds__(256, 2)
void k_gemm_conv(const float* __restrict__ A,
                 const __nv_bfloat16* __restrict__ Bhi, const __nv_bfloat16* __restrict__ Blo,
                 __half* __restrict__ C, int nrows) {
    constexpr int NC = 64;
    constexpr int WN = 16, NT = 2;
    constexpr int B_BYTES = NC * ROWB;
    constexpr int A_BYTES = 64 * ROWB;

    extern __shared__ char smem[];
    char* sBhi = smem;
    char* sBlo = smem + B_BYTES;
    char* sAhi = sBlo + B_BYTES;
    char* sAlo = sAhi + A_BYTES;

    const int nh = blockIdx.x & 1;
    const int cta = blockIdx.x >> 1;
    const int nctas = gridDim.x >> 1;

    const int tid = threadIdx.x;
    const int lane = tid & 31;
    const int wid = tid >> 5;
    const int g = lane >> 2;
    const int tg = lane & 3;
    const int mbase = (wid & 1) * 32;
    const int nbase = (wid >> 1) * WN;

    const __nv_bfloat16* Bh = Bhi + nh * 64 * 128;
    const __nv_bfloat16* Bl = Blo + nh * 64 * 128;

    // stage B hi/lo once
    for (int i = tid; i < NC * 16; i += 256) {
        int n = i >> 4, q = i & 15;
        *reinterpret_cast<uint4*>(sBhi + n * ROWB + q * 16) =
            reinterpret_cast<const uint4*>(Bh + n * 128)[q];
        *reinterpret_cast<uint4*>(sBlo + n * ROWB + q * 16) =
            reinterpret_cast<const uint4*>(Bl + n * 128)[q];
    }

    // ldmatrix base addresses
    const int rlm = lane & 7;
    const int qa = lane >> 3;
    uint32_t aAhi[2], aAlo[2];
#pragma unroll
    for (int mt = 0; mt < 2; mt++) {
        int row = mbase + mt * 16 + (qa & 1) * 8 + rlm;
        int col = (qa >> 1) * 16;
        aAhi[mt] = (uint32_t)__cvta_generic_to_shared(sAhi) + row * ROWB + col;
        aAlo[mt] = (uint32_t)__cvta_generic_to_shared(sAlo) + row * ROWB + col;
    }
    const int lb = lane & 15;
    uint32_t aBhi[NT], aBlo[NT];
#pragma unroll
    for (int nt = 0; nt < NT; nt++) {
        int row = nbase + nt * 8 + (lb & 7);
        int col = ((lb >> 3) & 1) * 16;
        aBhi[nt] = (uint32_t)__cvta_generic_to_shared(sBhi) + row * ROWB + col;
        aBlo[nt] = (uint32_t)__cvta_generic_to_shared(sBlo) + row * ROWB + col;
    }

    const int ntiles = (nrows + 63) / 64;
    const int m0 = tid >> 5;    // rows m0, m0+8, ..., m0+56
    const int q0 = tid & 31;    // float4 column

    // prologue: load first tile into registers
    float4 v[8];
    {
        const int r0 = cta * 64;
#pragma unroll
        for (int it = 0; it < 8; it++) {
            int gr = r0 + m0 + it * 8;
            v[it] = (gr < nrows && cta < ntiles)
                ? *reinterpret_cast<const float4*>(A + (size_t)gr * 128 + q0 * 4)
                : make_float4(0.f, 0.f, 0.f, 0.f);
        }
    }

    for (int t = cta; t < ntiles; t += nctas) {
        // convert + store registers -> smem
#pragma unroll
        for (int it = 0; it < 8; it++) {
            int m = m0 + it * 8;
            __nv_bfloat162 h01 = __float22bfloat162_rn(make_float2(v[it].x, v[it].y));
            __nv_bfloat162 h23 = __float22bfloat162_rn(make_float2(v[it].z, v[it].w));
            float2 f01 = __bfloat1622float2(h01);
            float2 f23 = __bfloat1622float2(h23);
            __nv_bfloat162 l01 = __float22bfloat162_rn(make_float2(v[it].x - f01.x, v[it].y - f01.y));
            __nv_bfloat162 l23 = __float22bfloat162_rn(make_float2(v[it].z - f23.x, v[it].w - f23.y));
            *reinterpret_cast<uint2*>(sAhi + m * ROWB + q0 * 8) = make_uint2(
                *reinterpret_cast<uint32_t*>(&h01), *reinterpret_cast<uint32_t*>(&h23));
            *reinterpret_cast<uint2*>(sAlo + m * ROWB + q0 * 8) = make_uint2(
                *reinterpret_cast<uint32_t*>(&l01), *reinterpret_cast<uint32_t*>(&l23));
        }
        __syncthreads();  // A (and B, first iter) visible to all

        // prefetch next tile into registers — lands during the MMA phase
        const int tn = t + nctas;
        if (tn < ntiles) {
            const int rn = tn * 64;
#pragma unroll
            for (int it = 0; it < 8; it++) {
                int gr = rn + m0 + it * 8;
                v[it] = (gr < nrows)
                    ? *reinterpret_cast<const float4*>(A + (size_t)gr * 128 + q0 * 4)
                    : make_float4(0.f, 0.f, 0.f, 0.f);
            }
        }

        // MMA from smem
        float acc[2][NT][4];
#pragma unroll
        for (int mt = 0; mt < 2; mt++)
#pragma unroll
            for (int nt = 0; nt < NT; nt++)
#pragma unroll
                for (int j = 0; j < 4; j++) acc[mt][nt][j] = 0.0f;

#pragma unroll
        for (int ks = 0; ks < 8; ks++) {
            const uint32_t ko = ks * 32;
            uint32_t ah[2][4], al[2][4];
#pragma unroll
            for (int mt = 0; mt < 2; mt++) {
                LDMX4(ah[mt][0], ah[mt][1], ah[mt][2], ah[mt][3], aAhi[mt] + ko);
                LDMX4(al[mt][0], al[mt][1], al[mt][2], al[mt][3], aAlo[mt] + ko);
            }
#pragma unroll
            for (int nt = 0; nt < NT; nt++) {
                uint32_t bh0, bh1, bl0, bl1;
                LDMX2(bh0, bh1, aBhi[nt] + ko);
                LDMX2(bl0, bl1, aBlo[nt] + ko);
#pragma unroll
                for (int mt = 0; mt < 2; mt++) {
                    MMA_BF16(acc[mt][nt], ah[mt], bh0, bh1);
                    MMA_BF16(acc[mt][nt], ah[mt], bl0, bl1);
                    MMA_BF16(acc[mt][nt], al[mt], bh0, bh1);
                }
            }
        }

        // epilogue
        const int r0 = t * 64;
#pragma unroll
        for (int mt = 0; mt < 2; mt++) {
#pragma unroll
            for (int nt = 0; nt < NT; nt++) {
                int r1 = r0 + mbase + mt * 16 + g;
                int r2 = r1 + 8;
                int cc = nh * 64 + nbase + nt * 8 + tg * 2;
                if (r1 < nrows)
                    *reinterpret_cast<__half2*>(C + (size_t)r1 * 128 + cc) =
                        __floats2half2_rn(acc[mt][nt][0], acc[mt][nt][1]);
                if (r2 < nrows)
                    *reinterpret_cast<__half2*>(C + (size_t)r2 * 128 + cc) =
                        __floats2half2_rn(acc[mt][nt][2], acc[mt][nt][3]);
            }
        }
        __syncthreads();  // smem A free for next convert_store
    }
}

// ---------------- GEMM2: pre-split bf16 A planes (unchanged R8) --------------
__global__ __launch_bounds__(256, 3)
void k_gemm_pre(const __nv_bfloat16* __restrict__ Ahi, const __nv_bfloat16* __restrict__ Alo,
                const __nv_bfloat16* __restrict__ Bhi, const __nv_bfloat16* __restrict__ Blo,
                __half* __restrict__ C, int nrows) {
    constexpr int NCOL = 64;
    constexpr int WN = 16, NT = 2;
    constexpr int B_BYTES = NCOL * ROWB;
    constexpr int A_BYTES = 64 * ROWB;

    extern __shared__ char smem[];
    char* sBhi = smem;
    char* sBlo = smem + B_BYTES;
    char* sAhi = sBlo + B_BYTES;
    char* sAlo = sAhi + A_BYTES;

    const int tid = threadIdx.x;
    const int lane = tid & 31;
    const int wid = tid >> 5;
    const int g = lane >> 2;
    const int tg = lane & 3;
    const int mbase = (wid & 1) * 32;
    const int nbase = (wid >> 1) * WN;

    for (int i = tid; i < NCOL * 16; i += 256) {
        int n = i >> 4, q = i & 15;
        *reinterpret_cast<uint4*>(sBhi + n * ROWB + q * 16) =
            reinterpret_cast<const uint4*>(Bhi + n * 128)[q];
        *reinterpret_cast<uint4*>(sBlo + n * ROWB + q * 16) =
            reinterpret_cast<const uint4*>(Blo + n * 128)[q];
    }

    const int rlm = lane & 7;
    const int qa = lane >> 3;
    uint32_t aAhi[2], aAlo[2];
#pragma unroll
    for (int mt = 0; mt < 2; mt++) {
        int row = mbase + mt * 16 + (qa & 1) * 8 + rlm;
        int col = (qa >> 1) * 16;
        aAhi[mt] = (uint32_t)__cvta_generic_to_shared(sAhi) + row * ROWB + col;
        aAlo[mt] = (uint32_t)__cvta_generic_to_shared(sAlo) + row * ROWB + col;
    }
    const int lb = lane & 15;
    uint32_t aBhi[NT], aBlo[NT];
#pragma unroll
    for (int nt = 0; nt < NT; nt++) {
        int row = nbase + nt * 8 + (lb & 7);
        int col = ((lb >> 3) & 1) * 16;
        aBhi[nt] = (uint32_t)__cvta_generic_to_shared(sBhi) + row * ROWB + col;
        aBlo[nt] = (uint32_t)__cvta_generic_to_shared(sBlo) + row * ROWB + col;
    }

    const int ntiles = (nrows + 63) / 64;
    for (int t = blockIdx.x; t < ntiles; t += gridDim.x) {
        const int r0 = t * 64;
        __syncthreads();

        uint4 v[8];
        const int half = tid >> 7;
        const int m0 = (tid & 127) >> 4;
        const int q0 = tid & 15;
        const __nv_bfloat16* Ap = half ? Alo : Ahi;
        char* sp = half ? sAlo : sAhi;
#pragma unroll
        for (int it = 0; it < 8; it++) {
            int gr = r0 + m0 + it * 8;
            v[it] = (gr < nrows)
                ? reinterpret_cast<const uint4*>(Ap + (size_t)gr * 128)[q0]
                : make_uint4(0u, 0u, 0u, 0u);
        }
#pragma unroll
        for (int it = 0; it < 8; it++)
            *reinterpret_cast<uint4*>(sp + (m0 + it * 8) * ROWB + q0 * 16) = v[it];
        __syncthreads();

        float acc[2][NT][4];
#pragma unroll
        for (int mt = 0; mt < 2; mt++)
#pragma unroll
            for (int nt = 0; nt < NT; nt++)
#pragma unroll
                for (int j = 0; j < 4; j++) acc[mt][nt][j] = 0.0f;

#pragma unroll
        for (int ks = 0; ks < 8; ks++) {
            const uint32_t ko = ks * 32;
            uint32_t ah[2][4], al[2][4];
#pragma unroll
            for (int mt = 0; mt < 2; mt++) {
                LDMX4(ah[mt][0], ah[mt][1], ah[mt][2], ah[mt][3], aAhi[mt] + ko);
                LDMX4(al[mt][0], al[mt][1], al[mt][2], al[mt][3], aAlo[mt] + ko);
            }
#pragma unroll
            for (int nt = 0; nt < NT; nt++) {
                uint32_t bh0, bh1, bl0, bl1;
                LDMX2(bh0, bh1, aBhi[nt] + ko);
                LDMX2(bl0, bl1, aBlo[nt] + ko);
#pragma unroll
                for (int mt = 0; mt < 2; mt++) {
                    MMA_BF16(acc[mt][nt], ah[mt], bh0, bh1);
                    MMA_BF16(acc[mt][nt], ah[mt], bl0, bl1);
                    MMA_BF16(acc[mt][nt], al[mt], bh0, bh1);
                }
            }
        }

#pragma unroll
        for (int mt = 0; mt < 2; mt++) {
#pragma unroll
            for (int nt = 0; nt < NT; nt++) {
                int r1 = r0 + mbase + mt * 16 + g;
                int r2 = r1 + 8;
                int cc = nbase + nt * 8 + tg * 2;
                if (r1 < nrows)
                    *reinterpret_cast<__half2*>(C + (size_t)r1 * NCOL + cc) =
                        __floats2half2_rn(acc[mt][nt][0], acc[mt][nt][1]);
                if (r2 < nrows)
                    *reinterpret_cast<__half2*>(C + (size_t)r2 * NCOL + cc) =
                        __floats2half2_rn(acc[mt][nt][2], acc[mt][nt][3]);
            }
        }
    }
}

// ---------------- agg1: mean + relu, fp16 in -> bf16 hi/lo out ---------------
__global__ void k_agg1(const __half* __restrict__ src,
                       __nv_bfloat16* __restrict__ dhi, __nv_bfloat16* __restrict__ dlo) {
    const int gw = (blockIdx.x * blockDim.x + threadIdx.x) >> 5;
    if (gw >= NN) return;
    const int lane = threadIdx.x & 31;

    const int d = g_deg[gw];
    const int cnt = d < CAP ? d : CAP;
    const int* __restrict__ adj = g_adj + (size_t)gw * CAP;

    float acc[4] = {0.f, 0.f, 0.f, 0.f};
#pragma unroll 4
    for (int t = 0; t < cnt; t++) {
        int j = __ldg(&adj[t]);
        uint2 v = *reinterpret_cast<const uint2*>(src + (size_t)j * 128 + lane * 4);
        float2 f0 = __half22float2(*reinterpret_cast<__half2*>(&v.x));
        float2 f1 = __half22float2(*reinterpret_cast<__half2*>(&v.y));
        acc[0] += f0.x; acc[1] += f0.y; acc[2] += f1.x; acc[3] += f1.y;
    }

    const float inv = 1.0f / (float)d;
    float o0 = fmaxf(acc[0] * inv, 0.f), o1 = fmaxf(acc[1] * inv, 0.f);
    float o2 = fmaxf(acc[2] * inv, 0.f), o3 = fmaxf(acc[3] * inv, 0.f);

    __nv_bfloat162 h01 = __float22bfloat162_rn(make_float2(o0, o1));
    __nv_bfloat162 h23 = __float22bfloat162_rn(make_float2(o2, o3));
    float2 f01 = __bfloat1622float2(h01);
    float2 f23 = __bfloat1622float2(h23);
    __nv_bfloat162 l01 = __float22bfloat162_rn(make_float2(o0 - f01.x, o1 - f01.y));
    __nv_bfloat162 l23 = __float22bfloat162_rn(make_float2(o2 - f23.x, o3 - f23.y));

    size_t off = (size_t)gw * 128 + lane * 4;
    *reinterpret_cast<uint2*>(dhi + off) = make_uint2(
        *reinterpret_cast<uint32_t*>(&h01), *reinterpret_cast<uint32_t*>(&h23));
    *reinterpret_cast<uint2*>(dlo + off) = make_uint2(
        *reinterpret_cast<uint32_t*>(&l01), *reinterpret_cast<uint32_t*>(&l23));
}

// ---------------- agg2: mean, fp16 in -> fp32 out -----------------------------
__global__ void k_agg2(const __half* __restrict__ src, float* __restrict__ dst) {
    const int gw = (blockIdx.x * blockDim.x + threadIdx.x) >> 5;
    if (gw >= NN) return;
    const int lane = threadIdx.x & 31;

    const int d = g_deg[gw];
    const int cnt = d < CAP ? d : CAP;
    const int* __restrict__ adj = g_adj + (size_t)gw * CAP;

    float acc0 = 0.f, acc1 = 0.f;
#pragma unroll 4
    for (int t = 0; t < cnt; t++) {
        int j = __ldg(&adj[t]);
        uint32_t v = *reinterpret_cast<const uint32_t*>(src + (size_t)j * 64 + lane * 2);
        float2 f = __half22float2(*reinterpret_cast<__half2*>(&v));
        acc0 += f.x; acc1 += f.y;
    }
    const float inv = 1.0f / (float)d;
    *reinterpret_cast<float2*>(dst + (size_t)gw * 64 + lane * 2) =
        make_float2(acc0 * inv, acc1 * inv);
}

// ---------------- launch --------------------------------------------------------
extern "C" void kernel_launch(void* const* d_in, const int* in_sizes, int n_in,
                              void* d_out, int out_size) {
    const float* x    = (const float*)d_in[0];
    const float* W1   = (const float*)d_in[1];
    const float* W2   = (const float*)d_in[2];
    const int*   erow = (const int*)d_in[3];
    const int*   ecol = (const int*)d_in[4];
    float* out = (float*)d_out;

    __half *h0, *h2;
    __nv_bfloat16 *h1hi, *h1lo, *w1hi, *w1lo, *w2hi, *w2lo;
    cudaGetSymbolAddress((void**)&h0,   g_h0);
    cudaGetSymbolAddress((void**)&h1hi, g_h1hi);
    cudaGetSymbolAddress((void**)&h1lo, g_h1lo);
    cudaGetSymbolAddress((void**)&h2,   g_h2);
    cudaGetSymbolAddress((void**)&w1hi, g_w1hi);
    cudaGetSymbolAddress((void**)&w1lo, g_w1lo);
    cudaGetSymbolAddress((void**)&w2hi, g_w2hi);
    cudaGetSymbolAddress((void**)&w2lo, g_w2lo);

    const int SMEM = 2 * 64 * ROWB + 2 * 64 * ROWB;   // 69632
    cudaFuncSetAttribute(k_gemm_conv, cudaFuncAttributeMaxDynamicSharedMemorySize, SMEM);
    cudaFuncSetAttribute(k_gemm_pre,  cudaFuncAttributeMaxDynamicSharedMemorySize, SMEM);

    // fork a side stream so build_adj overlaps prep + gemm1 (all independent)
    cudaStream_t s2;
    cudaStreamCreateWithFlags(&s2, cudaStreamNonBlocking);
    cudaEvent_t evFork, evJoin;
    cudaEventCreateWithFlags(&evFork, cudaEventDisableTiming);
    cudaEventCreateWithFlags(&evJoin, cudaEventDisableTiming);

    k_prep_w1<<<(NN + 255) / 256, 256>>>(W1, w1hi, w1lo);                         // 1
    cudaEventRecord(evFork, 0);
    cudaStreamWaitEvent(s2, evFork, 0);
    k_build_adj<<<(EE / 4 + 255) / 256, 256, 0, s2>>>(erow, ecol);                // side
    cudaEventRecord(evJoin, s2);

    k_prep_w2<<<(128 * 64 + 255) / 256, 256>>>(W2, w2hi, w2lo);                   // 2
    k_gemm_conv<<<2 * NSM, 256, SMEM>>>(x, w1hi, w1lo, h0, NN);                   // 3 (main)

    cudaStreamWaitEvent(0, evJoin, 0);   // adjacency ready before agg1
    k_agg1<<<(NN * 32 + 255) / 256, 256>>>(h0, h1hi, h1lo);                       // 4
    k_gemm_pre<<<3 * NSM, 256, SMEM>>>(h1hi, h1lo, w2hi, w2lo, h2, NN);           // 5
    k_agg2<<<(NN * 32 + 255) / 256, 256>>>(h2, out);                              // 6

    cudaEventDestroy(evFork);
    cudaEventDestroy(evJoin);
    cudaStreamDestroy(s2);
}

// round 10
// speedup vs baseline: 1.0862x; 1.0113x over previous
#include <cuda_runtime.h>
#include <cuda_bf16.h>
#include <cuda_fp16.h>
#include <cstdint>

// Problem constants (fixed by the dataset)
#define NN   100000      // nodes
#define EE   1600000     // edges
#define CAP  128         // adjacency bucket capacity per node
#define NSM  152         // GB300 SM count

// ---------------- scratch (device globals; no allocation allowed) ----------
__device__ __half         g_h0[(size_t)NN * 128];   // x @ W1 (fp16)
__device__ __nv_bfloat16  g_h1hi[(size_t)NN * 128]; // relu(agg h0), bf16 hi
__device__ __nv_bfloat16  g_h1lo[(size_t)NN * 128]; // bf16 lo plane
__device__ __half         g_h2[(size_t)NN * 64];    // h1 @ W2 (fp16)
__device__ int            g_deg[NN];
__device__ int            g_adj[(size_t)NN * CAP];
__device__ __nv_bfloat16  g_w1hi[128 * 128], g_w1lo[128 * 128];
__device__ __nv_bfloat16  g_w2hi[64 * 128],  g_w2lo[64 * 128];

#define ROWB 272   // smem row pitch: 128 bf16 (256B) + 16B pad, ldmatrix conflict-free

// ---------------- prep 1: clear degrees + W1 hi/lo transpose ----------------
__global__ void k_prep_w1(const float* __restrict__ W1,
                          __nv_bfloat16* __restrict__ w1hi, __nv_bfloat16* __restrict__ w1lo) {
    int i = blockIdx.x * blockDim.x + threadIdx.x;
    if (i < NN) g_deg[i] = 0;
    if (i < 128 * 128) {
        int k = i / 128, n = i % 128;
        float w = W1[i];
        __nv_bfloat16 h = __float2bfloat16_rn(w);
        w1hi[n * 128 + k] = h;
        w1lo[n * 128 + k] = __float2bfloat16_rn(w - __bfloat162float(h));
    }
}

// ---------------- prep 2: W2 hi/lo transpose --------------------------------
__global__ void k_prep_w2(const float* __restrict__ W2,
                          __nv_bfloat16* __restrict__ w2hi, __nv_bfloat16* __restrict__ w2lo) {
    int i = blockIdx.x * blockDim.x + threadIdx.x;
    if (i < 128 * 64) {
        int k = i / 64, n = i % 64;
        float w = W2[i];
        __nv_bfloat16 h = __float2bfloat16_rn(w);
        w2hi[n * 128 + k] = h;
        w2lo[n * 128 + k] = __float2bfloat16_rn(w - __bfloat162float(h));
    }
}

// ---------------- adjacency build: 4 edges/thread ---------------------------
__global__ void k_build_adj(const int* __restrict__ erow,
                            const int* __restrict__ ecol) {
    int e0 = (blockIdx.x * blockDim.x + threadIdx.x) * 4;
    if (e0 >= EE) return;
    int4 r = *reinterpret_cast<const int4*>(erow + e0);
    int4 c = *reinterpret_cast<const int4*>(ecol + e0);
    int p0 = atomicAdd(&g_deg[r.x], 1);
    int p1 = atomicAdd(&g_deg[r.y], 1);
    int p2 = atomicAdd(&g_deg[r.z], 1);
    int p3 = atomicAdd(&g_deg[r.w], 1);
    if (p0 < CAP) g_adj[(size_t)r.x * CAP + p0] = c.x;
    if (p1 < CAP) g_adj[(size_t)r.y * CAP + p1] = c.y;
    if (p2 < CAP) g_adj[(size_t)r.z * CAP + p2] = c.z;
    if (p3 < CAP) g_adj[(size_t)r.w * CAP + p3] = c.w;
}

// ---------------- mma / ldmatrix helpers -------------------------------------
#define LDMX4(r0, r1, r2, r3, addr) \
    asm volatile("ldmatrix.sync.aligned.m8n8.x4.shared.b16 {%0,%1,%2,%3}, [%4];" \
                 : "=r"(r0), "=r"(r1), "=r"(r2), "=r"(r3) : "r"(addr))
#define LDMX2(r0, r1, addr) \
    asm volatile("ldmatrix.sync.aligned.m8n8.x2.shared.b16 {%0,%1}, [%2];" \
                 : "=r"(r0), "=r"(r1) : "r"(addr))
#define MMA_BF16(acc, a, b0, b1) \
    asm volatile("mma.sync.aligned.m16n8k16.row.col.f32.bf16.bf16.f32 " \
                 "{%0,%1,%2,%3}, {%4,%5,%6,%7}, {%8,%9}, {%0,%1,%2,%3};" \
                 : "+f"(acc[0]), "+f"(acc[1]), "+f"(acc[2]), "+f"(acc[3]) \
                 : "r"(a[0]), "r"(a[1]), "r"(a[2]), "r"(a[3]), "r"(b0), "r"(b1))

// ---------------- GEMM1: fp32 A -> bf16 hi/lo, reg-prefetch, split-acc -------
// Output C[nrows,128](fp16). CTA tile 64 rows x 64 cols (nh = blockIdx.x & 1).
// 3 independent accumulator sets (one per Dekker pass) -> 12 MMA chains/warp.
__global__ __launch_bounds__(256, 2)
void k_gemm_conv(const float* __restrict__ A,
                 const __nv_bfloat16* __restrict__ Bhi, const __nv_bfloat16* __restrict__ Blo,
                 __half* __restrict__ C, int nrows) {
    constexpr int NC = 64;
    constexpr int WN = 16, NT = 2;
    constexpr int B_BYTES = NC * ROWB;
    constexpr int A_BYTES = 64 * ROWB;

    extern __shared__ char smem[];
    char* sBhi = smem;
    char* sBlo = smem + B_BYTES;
    char* sAhi = sBlo + B_BYTES;
    char* sAlo = sAhi + A_BYTES;

    const int nh = blockIdx.x & 1;
    const int cta = blockIdx.x >> 1;
    const int nctas = gridDim.x >> 1;

    const int tid = threadIdx.x;
    const int lane = tid & 31;
    const int wid = tid >> 5;
    const int g = lane >> 2;
    const int tg = lane & 3;
    const int mbase = (wid & 1) * 32;
    const int nbase = (wid >> 1) * WN;

    const __nv_bfloat16* Bh = Bhi + nh * 64 * 128;
    const __nv_bfloat16* Bl = Blo + nh * 64 * 128;

    // stage B hi/lo once
    for (int i = tid; i < NC * 16; i += 256) {
        int n = i >> 4, q = i & 15;
        *reinterpret_cast<uint4*>(sBhi + n * ROWB + q * 16) =
            reinterpret_cast<const uint4*>(Bh + n * 128)[q];
        *reinterpret_cast<uint4*>(sBlo + n * ROWB + q * 16) =
            reinterpret_cast<const uint4*>(Bl + n * 128)[q];
    }

    // ldmatrix base addresses
    const int rlm = lane & 7;
    const int qa = lane >> 3;
    uint32_t aAhi[2], aAlo[2];
#pragma unroll
    for (int mt = 0; mt < 2; mt++) {
        int row = mbase + mt * 16 + (qa & 1) * 8 + rlm;
        int col = (qa >> 1) * 16;
        aAhi[mt] = (uint32_t)__cvta_generic_to_shared(sAhi) + row * ROWB + col;
        aAlo[mt] = (uint32_t)__cvta_generic_to_shared(sAlo) + row * ROWB + col;
    }
    const int lb = lane & 15;
    uint32_t aBhi[NT], aBlo[NT];
#pragma unroll
    for (int nt = 0; nt < NT; nt++) {
        int row = nbase + nt * 8 + (lb & 7);
        int col = ((lb >> 3) & 1) * 16;
        aBhi[nt] = (uint32_t)__cvta_generic_to_shared(sBhi) + row * ROWB + col;
        aBlo[nt] = (uint32_t)__cvta_generic_to_shared(sBlo) + row * ROWB + col;
    }

    const int ntiles = (nrows + 63) / 64;
    const int m0 = tid >> 5;
    const int q0 = tid & 31;

    // prologue: load first tile into registers
    float4 v[8];
    {
        const int r0 = cta * 64;
#pragma unroll
        for (int it = 0; it < 8; it++) {
            int gr = r0 + m0 + it * 8;
            v[it] = (gr < nrows && cta < ntiles)
                ? *reinterpret_cast<const float4*>(A + (size_t)gr * 128 + q0 * 4)
                : make_float4(0.f, 0.f, 0.f, 0.f);
        }
    }

    for (int t = cta; t < ntiles; t += nctas) {
        // convert + store registers -> smem
#pragma unroll
        for (int it = 0; it < 8; it++) {
            int m = m0 + it * 8;
            __nv_bfloat162 h01 = __float22bfloat162_rn(make_float2(v[it].x, v[it].y));
            __nv_bfloat162 h23 = __float22bfloat162_rn(make_float2(v[it].z, v[it].w));
            float2 f01 = __bfloat1622float2(h01);
            float2 f23 = __bfloat1622float2(h23);
            __nv_bfloat162 l01 = __float22bfloat162_rn(make_float2(v[it].x - f01.x, v[it].y - f01.y));
            __nv_bfloat162 l23 = __float22bfloat162_rn(make_float2(v[it].z - f23.x, v[it].w - f23.y));
            *reinterpret_cast<uint2*>(sAhi + m * ROWB + q0 * 8) = make_uint2(
                *reinterpret_cast<uint32_t*>(&h01), *reinterpret_cast<uint32_t*>(&h23));
            *reinterpret_cast<uint2*>(sAlo + m * ROWB + q0 * 8) = make_uint2(
                *reinterpret_cast<uint32_t*>(&l01), *reinterpret_cast<uint32_t*>(&l23));
        }
        __syncthreads();

        // prefetch next tile — lands during the MMA phase
        const int tn = t + nctas;
        if (tn < ntiles) {
            const int rn = tn * 64;
#pragma unroll
            for (int it = 0; it < 8; it++) {
                int gr = rn + m0 + it * 8;
                v[it] = (gr < nrows)
                    ? *reinterpret_cast<const float4*>(A + (size_t)gr * 128 + q0 * 4)
                    : make_float4(0.f, 0.f, 0.f, 0.f);
            }
        }

        // MMA: 3 independent accumulator sets (HH, HL, LH)
        float accHH[2][NT][4], accHL[2][NT][4], accLH[2][NT][4];
#pragma unroll
        for (int mt = 0; mt < 2; mt++)
#pragma unroll
            for (int nt = 0; nt < NT; nt++)
#pragma unroll
                for (int j = 0; j < 4; j++) {
                    accHH[mt][nt][j] = 0.0f;
                    accHL[mt][nt][j] = 0.0f;
                    accLH[mt][nt][j] = 0.0f;
                }

#pragma unroll
        for (int ks = 0; ks < 8; ks++) {
            const uint32_t ko = ks * 32;
            uint32_t ah[2][4], al[2][4];
#pragma unroll
            for (int mt = 0; mt < 2; mt++) {
                LDMX4(ah[mt][0], ah[mt][1], ah[mt][2], ah[mt][3], aAhi[mt] + ko);
                LDMX4(al[mt][0], al[mt][1], al[mt][2], al[mt][3], aAlo[mt] + ko);
            }
#pragma unroll
            for (int nt = 0; nt < NT; nt++) {
                uint32_t bh0, bh1, bl0, bl1;
                LDMX2(bh0, bh1, aBhi[nt] + ko);
                LDMX2(bl0, bl1, aBlo[nt] + ko);
#pragma unroll
                for (int mt = 0; mt < 2; mt++) {
                    MMA_BF16(accHH[mt][nt], ah[mt], bh0, bh1);
                    MMA_BF16(accHL[mt][nt], ah[mt], bl0, bl1);
                    MMA_BF16(accLH[mt][nt], al[mt], bh0, bh1);
                }
            }
        }

        // epilogue: sum passes, fp16 out
        const int r0 = t * 64;
#pragma unroll
        for (int mt = 0; mt < 2; mt++) {
#pragma unroll
            for (int nt = 0; nt < NT; nt++) {
                float s0 = accHH[mt][nt][0] + (accHL[mt][nt][0] + accLH[mt][nt][0]);
                float s1 = accHH[mt][nt][1] + (accHL[mt][nt][1] + accLH[mt][nt][1]);
                float s2 = accHH[mt][nt][2] + (accHL[mt][nt][2] + accLH[mt][nt][2]);
                float s3 = accHH[mt][nt][3] + (accHL[mt][nt][3] + accLH[mt][nt][3]);
                int r1 = r0 + mbase + mt * 16 + g;
                int r2 = r1 + 8;
                int cc = nh * 64 + nbase + nt * 8 + tg * 2;
                if (r1 < nrows)
                    *reinterpret_cast<__half2*>(C + (size_t)r1 * 128 + cc) =
                        __floats2half2_rn(s0, s1);
                if (r2 < nrows)
                    *reinterpret_cast<__half2*>(C + (size_t)r2 * 128 + cc) =
                        __floats2half2_rn(s2, s3);
            }
        }
        __syncthreads();
    }
}

// ---------------- GEMM2: pre-split bf16 A, reg-prefetch, split-acc -----------
__global__ __launch_bounds__(256, 2)
void k_gemm_pre(const __nv_bfloat16* __restrict__ Ahi, const __nv_bfloat16* __restrict__ Alo,
                const __nv_bfloat16* __restrict__ Bhi, const __nv_bfloat16* __restrict__ Blo,
                __half* __restrict__ C, int nrows) {
    constexpr int NCOL = 64;
    constexpr int WN = 16, NT = 2;
    constexpr int B_BYTES = NCOL * ROWB;
    constexpr int A_BYTES = 64 * ROWB;

    extern __shared__ char smem[];
    char* sBhi = smem;
    char* sBlo = smem + B_BYTES;
    char* sAhi = sBlo + B_BYTES;
    char* sAlo = sAhi + A_BYTES;

    const int tid = threadIdx.x;
    const int lane = tid & 31;
    const int wid = tid >> 5;
    const int g = lane >> 2;
    const int tg = lane & 3;
    const int mbase = (wid & 1) * 32;
    const int nbase = (wid >> 1) * WN;

    for (int i = tid; i < NCOL * 16; i += 256) {
        int n = i >> 4, q = i & 15;
        *reinterpret_cast<uint4*>(sBhi + n * ROWB + q * 16) =
            reinterpret_cast<const uint4*>(Bhi + n * 128)[q];
        *reinterpret_cast<uint4*>(sBlo + n * ROWB + q * 16) =
            reinterpret_cast<const uint4*>(Blo + n * 128)[q];
    }

    const int rlm = lane & 7;
    const int qa = lane >> 3;
    uint32_t aAhi[2], aAlo[2];
#pragma unroll
    for (int mt = 0; mt < 2; mt++) {
        int row = mbase + mt * 16 + (qa & 1) * 8 + rlm;
        int col = (qa >> 1) * 16;
        aAhi[mt] = (uint32_t)__cvta_generic_to_shared(sAhi) + row * ROWB + col;
        aAlo[mt] = (uint32_t)__cvta_generic_to_shared(sAlo) + row * ROWB + col;
    }
    const int lb = lane & 15;
    uint32_t aBhi[NT], aBlo[NT];
#pragma unroll
    for (int nt = 0; nt < NT; nt++) {
        int row = nbase + nt * 8 + (lb & 7);
        int col = ((lb >> 3) & 1) * 16;
        aBhi[nt] = (uint32_t)__cvta_generic_to_shared(sBhi) + row * ROWB + col;
        aBlo[nt] = (uint32_t)__cvta_generic_to_shared(sBlo) + row * ROWB + col;
    }

    const int ntiles = (nrows + 63) / 64;
    const int half = tid >> 7;          // 0: hi plane, 1: lo plane
    const int m0 = (tid & 127) >> 4;
    const int q0 = tid & 15;
    const __nv_bfloat16* Ap = half ? Alo : Ahi;
    char* sp = half ? sAlo : sAhi;

    // prologue: load first tile into registers
    uint4 v[8];
    {
        const int r0 = blockIdx.x * 64;
#pragma unroll
        for (int it = 0; it < 8; it++) {
            int gr = r0 + m0 + it * 8;
            v[it] = (gr < nrows && (int)blockIdx.x < ntiles)
                ? reinterpret_cast<const uint4*>(Ap + (size_t)gr * 128)[q0]
                : make_uint4(0u, 0u, 0u, 0u);
        }
    }

    for (int t = blockIdx.x; t < ntiles; t += gridDim.x) {
        // store registers -> smem
#pragma unroll
        for (int it = 0; it < 8; it++)
            *reinterpret_cast<uint4*>(sp + (m0 + it * 8) * ROWB + q0 * 16) = v[it];
        __syncthreads();

        // prefetch next tile
        const int tn = t + gridDim.x;
        if (tn < ntiles) {
            const int rn = tn * 64;
#pragma unroll
            for (int it = 0; it < 8; it++) {
                int gr = rn + m0 + it * 8;
                v[it] = (gr < nrows)
                    ? reinterpret_cast<const uint4*>(Ap + (size_t)gr * 128)[q0]
                    : make_uint4(0u, 0u, 0u, 0u);
            }
        }

        float accHH[2][NT][4], accHL[2][NT][4], accLH[2][NT][4];
#pragma unroll
        for (int mt = 0; mt < 2; mt++)
#pragma unroll
            for (int nt = 0; nt < NT; nt++)
#pragma unroll
                for (int j = 0; j < 4; j++) {
                    accHH[mt][nt][j] = 0.0f;
                    accHL[mt][nt][j] = 0.0f;
                    accLH[mt][nt][j] = 0.0f;
                }

#pragma unroll
        for (int ks = 0; ks < 8; ks++) {
            const uint32_t ko = ks * 32;
            uint32_t ah[2][4], al[2][4];
#pragma unroll
            for (int mt = 0; mt < 2; mt++) {
                LDMX4(ah[mt][0], ah[mt][1], ah[mt][2], ah[mt][3], aAhi[mt] + ko);
                LDMX4(al[mt][0], al[mt][1], al[mt][2], al[mt][3], aAlo[mt] + ko);
            }
#pragma unroll
            for (int nt = 0; nt < NT; nt++) {
                uint32_t bh0, bh1, bl0, bl1;
                LDMX2(bh0, bh1, aBhi[nt] + ko);
                LDMX2(bl0, bl1, aBlo[nt] + ko);
#pragma unroll
                for (int mt = 0; mt < 2; mt++) {
                    MMA_BF16(accHH[mt][nt], ah[mt], bh0, bh1);
                    MMA_BF16(accHL[mt][nt], ah[mt], bl0, bl1);
                    MMA_BF16(accLH[mt][nt], al[mt], bh0, bh1);
                }
            }
        }

        const int r0 = t * 64;
#pragma unroll
        for (int mt = 0; mt < 2; mt++) {
#pragma unroll
            for (int nt = 0; nt < NT; nt++) {
                float s0 = accHH[mt][nt][0] + (accHL[mt][nt][0] + accLH[mt][nt][0]);
                float s1 = accHH[mt][nt][1] + (accHL[mt][nt][1] + accLH[mt][nt][1]);
                float s2 = accHH[mt][nt][2] + (accHL[mt][nt][2] + accLH[mt][nt][2]);
                float s3 = accHH[mt][nt][3] + (accHL[mt][nt][3] + accLH[mt][nt][3]);
                int r1 = r0 + mbase + mt * 16 + g;
                int r2 = r1 + 8;
                int cc = nbase + nt * 8 + tg * 2;
                if (r1 < nrows)
                    *reinterpret_cast<__half2*>(C + (size_t)r1 * NCOL + cc) =
                        __floats2half2_rn(s0, s1);
                if (r2 < nrows)
                    *reinterpret_cast<__half2*>(C + (size_t)r2 * NCOL + cc) =
                        __floats2half2_rn(s2, s3);
            }
        }
        __syncthreads();
    }
}

// ---------------- agg1: mean + relu, fp16 in -> bf16 hi/lo out ---------------
__global__ void k_agg1(const __half* __restrict__ src,
                       __nv_bfloat16* __restrict__ dhi, __nv_bfloat16* __restrict__ dlo) {
    const int gw = (blockIdx.x * blockDim.x + threadIdx.x) >> 5;
    if (gw >= NN) return;
    const int lane = threadIdx.x & 31;

    const int d = g_deg[gw];
    const int cnt = d < CAP ? d : CAP;
    const int* __restrict__ adj = g_adj + (size_t)gw * CAP;

    float acc[4] = {0.f, 0.f, 0.f, 0.f};
#pragma unroll 4
    for (int t = 0; t < cnt; t++) {
        int j = __ldg(&adj[t]);
        uint2 v = *reinterpret_cast<const uint2*>(src + (size_t)j * 128 + lane * 4);
        float2 f0 = __half22float2(*reinterpret_cast<__half2*>(&v.x));
        float2 f1 = __half22float2(*reinterpret_cast<__half2*>(&v.y));
        acc[0] += f0.x; acc[1] += f0.y; acc[2] += f1.x; acc[3] += f1.y;
    }

    const float inv = 1.0f / (float)d;
    float o0 = fmaxf(acc[0] * inv, 0.f), o1 = fmaxf(acc[1] * inv, 0.f);
    float o2 = fmaxf(acc[2] * inv, 0.f), o3 = fmaxf(acc[3] * inv, 0.f);

    __nv_bfloat162 h01 = __float22bfloat162_rn(make_float2(o0, o1));
    __nv_bfloat162 h23 = __float22bfloat162_rn(make_float2(o2, o3));
    float2 f01 = __bfloat1622float2(h01);
    float2 f23 = __bfloat1622float2(h23);
    __nv_bfloat162 l01 = __float22bfloat162_rn(make_float2(o0 - f01.x, o1 - f01.y));
    __nv_bfloat162 l23 = __float22bfloat162_rn(make_float2(o2 - f23.x, o3 - f23.y));

    size_t off = (size_t)gw * 128 + lane * 4;
    *reinterpret_cast<uint2*>(dhi + off) = make_uint2(
        *reinterpret_cast<uint32_t*>(&h01), *reinterpret_cast<uint32_t*>(&h23));
    *reinterpret_cast<uint2*>(dlo + off) = make_uint2(
        *reinterpret_cast<uint32_t*>(&l01), *reinterpret_cast<uint32_t*>(&l23));
}

// ---------------- agg2: mean, fp16 in -> fp32 out -----------------------------
__global__ void k_agg2(const __half* __restrict__ src, float* __restrict__ dst) {
    const int gw = (blockIdx.x * blockDim.x + threadIdx.x) >> 5;
    if (gw >= NN) return;
    const int lane = threadIdx.x & 31;

    const int d = g_deg[gw];
    const int cnt = d < CAP ? d : CAP;
    const int* __restrict__ adj = g_adj + (size_t)gw * CAP;

    float acc0 = 0.f, acc1 = 0.f;
#pragma unroll 4
    for (int t = 0; t < cnt; t++) {
        int j = __ldg(&adj[t]);
        uint32_t v = *reinterpret_cast<const uint32_t*>(src + (size_t)j * 64 + lane * 2);
        float2 f = __half22float2(*reinterpret_cast<__half2*>(&v));
        acc0 += f.x; acc1 += f.y;
    }
    const float inv = 1.0f / (float)d;
    *reinterpret_cast<float2*>(dst + (size_t)gw * 64 + lane * 2) =
        make_float2(acc0 * inv, acc1 * inv);
}

// ---------------- launch --------------------------------------------------------
extern "C" void kernel_launch(void* const* d_in, const int* in_sizes, int n_in,
                              void* d_out, int out_size) {
    const float* x    = (const float*)d_in[0];
    const float* W1   = (const float*)d_in[1];
    const float* W2   = (const float*)d_in[2];
    const int*   erow = (const int*)d_in[3];
    const int*   ecol = (const int*)d_in[4];
    float* out = (float*)d_out;

    __half *h0, *h2;
    __nv_bfloat16 *h1hi, *h1lo, *w1hi, *w1lo, *w2hi, *w2lo;
    cudaGetSymbolAddress((void**)&h0,   g_h0);
    cudaGetSymbolAddress((void**)&h1hi, g_h1hi);
    cudaGetSymbolAddress((void**)&h1lo, g_h1lo);
    cudaGetSymbolAddress((void**)&h2,   g_h2);
    cudaGetSymbolAddress((void**)&w1hi, g_w1hi);
    cudaGetSymbolAddress((void**)&w1lo, g_w1lo);
    cudaGetSymbolAddress((void**)&w2hi, g_w2hi);
    cudaGetSymbolAddress((void**)&w2lo, g_w2lo);

    const int SMEM = 2 * 64 * ROWB + 2 * 64 * ROWB;   // 69632
    cudaFuncSetAttribute(k_gemm_conv, cudaFuncAttributeMaxDynamicSharedMemorySize, SMEM);
    cudaFuncSetAttribute(k_gemm_pre,  cudaFuncAttributeMaxDynamicSharedMemorySize, SMEM);

    // fork a side stream so build_adj overlaps prep + gemm1
    cudaStream_t s2;
    cudaStreamCreateWithFlags(&s2, cudaStreamNonBlocking);
    cudaEvent_t evFork, evJoin;
    cudaEventCreateWithFlags(&evFork, cudaEventDisableTiming);
    cudaEventCreateWithFlags(&evJoin, cudaEventDisableTiming);

    k_prep_w1<<<(NN + 255) / 256, 256>>>(W1, w1hi, w1lo);                         // 1
    cudaEventRecord(evFork, 0);
    cudaStreamWaitEvent(s2, evFork, 0);
    k_build_adj<<<(EE / 4 + 255) / 256, 256, 0, s2>>>(erow, ecol);                // 2 (side)
    cudaEventRecord(evJoin, s2);

    k_prep_w2<<<(128 * 64 + 255) / 256, 256>>>(W2, w2hi, w2lo);                   // 3
    k_gemm_conv<<<2 * NSM, 256, SMEM>>>(x, w1hi, w1lo, h0, NN);                   // 4 (slot 4)

    cudaStreamWaitEvent(0, evJoin, 0);   // adjacency ready before agg1
    k_agg1<<<(NN * 32 + 255) / 256, 256>>>(h0, h1hi, h1lo);                       // 5
    k_gemm_pre<<<2 * NSM, 256, SMEM>>>(h1hi, h1lo, w2hi, w2lo, h2, NN);           // 6
    k_agg2<<<(NN * 32 + 255) / 256, 256>>>(h2, out);                              // 7

    cudaEventDestroy(evFork);
    cudaEventDestroy(evJoin);
    cudaStreamDestroy(s2);
}

// round 11
// speedup vs baseline: 1.1300x; 1.0403x over previous
#include <cuda_runtime.h>
#include <cuda_bf16.h>
#include <cuda_fp16.h>
#include <cstdint>

// Problem constants (fixed by the dataset)
#define NN   100000      // nodes
#define EE   1600000     // edges
#define CAP  128         // adjacency bucket capacity per node
#define NSM  152         // GB300 SM count

// ---------------- scratch (device globals; no allocation allowed) ----------
__device__ __half  g_h0[(size_t)NN * 128];   // x @ W1 (fp16)
__device__ __half  g_h1hi[(size_t)NN * 128]; // relu(agg h0), fp16 hi plane
__device__ __half  g_h1lo[(size_t)NN * 128]; // fp16 lo plane
__device__ __half  g_h2[(size_t)NN * 64];    // h1 @ W2 (fp16)
__device__ int     g_deg[NN];
__device__ int     g_adj[(size_t)NN * CAP];
__device__ __half  g_w1[128 * 128];          // W1^T, fp16
__device__ __half  g_w2[64 * 128];           // W2^T, fp16

#define ROWB 272   // smem row pitch: 128 halves (256B) + 16B pad, ldmatrix conflict-free

// ---------------- prep 1: clear degrees + W1 transpose -> fp16 ---------------
__global__ void k_prep_w1(const float* __restrict__ W1, __half* __restrict__ w1) {
    int i = blockIdx.x * blockDim.x + threadIdx.x;
    if (i < NN) g_deg[i] = 0;
    if (i < 128 * 128) {
        int k = i / 128, n = i % 128;
        w1[n * 128 + k] = __float2half_rn(W1[i]);
    }
}

// ---------------- prep 2: W2 transpose -> fp16 --------------------------------
__global__ void k_prep_w2(const float* __restrict__ W2, __half* __restrict__ w2) {
    int i = blockIdx.x * blockDim.x + threadIdx.x;
    if (i < 128 * 64) {
        int k = i / 64, n = i % 64;
        w2[n * 128 + k] = __float2half_rn(W2[i]);
    }
}

// ---------------- adjacency build: 4 edges/thread ---------------------------
__global__ void k_build_adj(const int* __restrict__ erow,
                            const int* __restrict__ ecol) {
    int e0 = (blockIdx.x * blockDim.x + threadIdx.x) * 4;
    if (e0 >= EE) return;
    int4 r = *reinterpret_cast<const int4*>(erow + e0);
    int4 c = *reinterpret_cast<const int4*>(ecol + e0);
    int p0 = atomicAdd(&g_deg[r.x], 1);
    int p1 = atomicAdd(&g_deg[r.y], 1);
    int p2 = atomicAdd(&g_deg[r.z], 1);
    int p3 = atomicAdd(&g_deg[r.w], 1);
    if (p0 < CAP) g_adj[(size_t)r.x * CAP + p0] = c.x;
    if (p1 < CAP) g_adj[(size_t)r.y * CAP + p1] = c.y;
    if (p2 < CAP) g_adj[(size_t)r.z * CAP + p2] = c.z;
    if (p3 < CAP) g_adj[(size_t)r.w * CAP + p3] = c.w;
}

// ---------------- mma / ldmatrix helpers -------------------------------------
#define LDMX4(r0, r1, r2, r3, addr) \
    asm volatile("ldmatrix.sync.aligned.m8n8.x4.shared.b16 {%0,%1,%2,%3}, [%4];" \
                 : "=r"(r0), "=r"(r1), "=r"(r2), "=r"(r3) : "r"(addr))
#define LDMX2(r0, r1, addr) \
    asm volatile("ldmatrix.sync.aligned.m8n8.x2.shared.b16 {%0,%1}, [%2];" \
                 : "=r"(r0), "=r"(r1) : "r"(addr))
#define MMA_F16(acc, a, b0, b1) \
    asm volatile("mma.sync.aligned.m16n8k16.row.col.f32.f16.f16.f32 " \
                 "{%0,%1,%2,%3}, {%4,%5,%6,%7}, {%8,%9}, {%0,%1,%2,%3};" \
                 : "+f"(acc[0]), "+f"(acc[1]), "+f"(acc[2]), "+f"(acc[3]) \
                 : "r"(a[0]), "r"(a[1]), "r"(a[2]), "r"(a[3]), "r"(b0), "r"(b1))

// ---------------- GEMM1: fp32 A -> fp16 hi/lo 2-pass, reg-prefetch -----------
// Output C[nrows,128](fp16). CTA tile 64 rows x 64 cols (nh = blockIdx.x & 1).
// C = Ah@B + Al@B, B single fp16 plane. 2 independent acc sets per (mt,nt).
__global__ __launch_bounds__(256, 2)
void k_gemm_conv(const float* __restrict__ A, const __half* __restrict__ B,
                 __half* __restrict__ C, int nrows) {
    constexpr int NC = 64;
    constexpr int WN = 16, NT = 2;
    constexpr int B_BYTES = NC * ROWB;
    constexpr int A_BYTES = 64 * ROWB;

    extern __shared__ char smem[];
    char* sB   = smem;
    char* sAhi = smem + B_BYTES;
    char* sAlo = sAhi + A_BYTES;

    const int nh = blockIdx.x & 1;
    const int cta = blockIdx.x >> 1;
    const int nctas = gridDim.x >> 1;

    const int tid = threadIdx.x;
    const int lane = tid & 31;
    const int wid = tid >> 5;
    const int g = lane >> 2;
    const int tg = lane & 3;
    const int mbase = (wid & 1) * 32;
    const int nbase = (wid >> 1) * WN;

    const __half* Bp = B + nh * 64 * 128;

    // stage B once (64 rows x 16 uint4)
    for (int i = tid; i < NC * 16; i += 256) {
        int n = i >> 4, q = i & 15;
        *reinterpret_cast<uint4*>(sB + n * ROWB + q * 16) =
            reinterpret_cast<const uint4*>(Bp + n * 128)[q];
    }

    // ldmatrix base addresses
    const int rlm = lane & 7;
    const int qa = lane >> 3;
    uint32_t aAhi[2], aAlo[2];
#pragma unroll
    for (int mt = 0; mt < 2; mt++) {
        int row = mbase + mt * 16 + (qa & 1) * 8 + rlm;
        int col = (qa >> 1) * 16;
        aAhi[mt] = (uint32_t)__cvta_generic_to_shared(sAhi) + row * ROWB + col;
        aAlo[mt] = (uint32_t)__cvta_generic_to_shared(sAlo) + row * ROWB + col;
    }
    const int lb = lane & 15;
    uint32_t aB[NT];
#pragma unroll
    for (int nt = 0; nt < NT; nt++) {
        int row = nbase + nt * 8 + (lb & 7);
        int col = ((lb >> 3) & 1) * 16;
        aB[nt] = (uint32_t)__cvta_generic_to_shared(sB) + row * ROWB + col;
    }

    const int ntiles = (nrows + 63) / 64;
    const int m0 = tid >> 5;
    const int q0 = tid & 31;

    // prologue: load first tile into registers
    float4 v[8];
    {
        const int r0 = cta * 64;
#pragma unroll
        for (int it = 0; it < 8; it++) {
            int gr = r0 + m0 + it * 8;
            v[it] = (gr < nrows && cta < ntiles)
                ? *reinterpret_cast<const float4*>(A + (size_t)gr * 128 + q0 * 4)
                : make_float4(0.f, 0.f, 0.f, 0.f);
        }
    }

    for (int t = cta; t < ntiles; t += nctas) {
        // convert + store registers -> smem (fp16 hi/lo Dekker split)
#pragma unroll
        for (int it = 0; it < 8; it++) {
            int m = m0 + it * 8;
            __half2 h01 = __float22half2_rn(make_float2(v[it].x, v[it].y));
            __half2 h23 = __float22half2_rn(make_float2(v[it].z, v[it].w));
            float2 f01 = __half22float2(h01);
            float2 f23 = __half22float2(h23);
            __half2 l01 = __float22half2_rn(make_float2(v[it].x - f01.x, v[it].y - f01.y));
            __half2 l23 = __float22half2_rn(make_float2(v[it].z - f23.x, v[it].w - f23.y));
            *reinterpret_cast<uint2*>(sAhi + m * ROWB + q0 * 8) = make_uint2(
                *reinterpret_cast<uint32_t*>(&h01), *reinterpret_cast<uint32_t*>(&h23));
            *reinterpret_cast<uint2*>(sAlo + m * ROWB + q0 * 8) = make_uint2(
                *reinterpret_cast<uint32_t*>(&l01), *reinterpret_cast<uint32_t*>(&l23));
        }
        __syncthreads();

        // prefetch next tile — lands during the MMA phase
        const int tn = t + nctas;
        if (tn < ntiles) {
            const int rn = tn * 64;
#pragma unroll
            for (int it = 0; it < 8; it++) {
                int gr = rn + m0 + it * 8;
                v[it] = (gr < nrows)
                    ? *reinterpret_cast<const float4*>(A + (size_t)gr * 128 + q0 * 4)
                    : make_float4(0.f, 0.f, 0.f, 0.f);
            }
        }

        // MMA: 2 independent accumulator sets (H pass, L pass)
        float accH[2][NT][4], accL[2][NT][4];
#pragma unroll
        for (int mt = 0; mt < 2; mt++)
#pragma unroll
            for (int nt = 0; nt < NT; nt++)
#pragma unroll
                for (int j = 0; j < 4; j++) {
                    accH[mt][nt][j] = 0.0f;
                    accL[mt][nt][j] = 0.0f;
                }

#pragma unroll
        for (int ks = 0; ks < 8; ks++) {
            const uint32_t ko = ks * 32;
            uint32_t ah[2][4], al[2][4];
#pragma unroll
            for (int mt = 0; mt < 2; mt++) {
                LDMX4(ah[mt][0], ah[mt][1], ah[mt][2], ah[mt][3], aAhi[mt] + ko);
                LDMX4(al[mt][0], al[mt][1], al[mt][2], al[mt][3], aAlo[mt] + ko);
            }
#pragma unroll
            for (int nt = 0; nt < NT; nt++) {
                uint32_t b0, b1;
                LDMX2(b0, b1, aB[nt] + ko);
#pragma unroll
                for (int mt = 0; mt < 2; mt++) {
                    MMA_F16(accH[mt][nt], ah[mt], b0, b1);
                    MMA_F16(accL[mt][nt], al[mt], b0, b1);
                }
            }
        }

        // epilogue: sum passes, fp16 out
        const int r0 = t * 64;
#pragma unroll
        for (int mt = 0; mt < 2; mt++) {
#pragma unroll
            for (int nt = 0; nt < NT; nt++) {
                float s0 = accH[mt][nt][0] + accL[mt][nt][0];
                float s1 = accH[mt][nt][1] + accL[mt][nt][1];
                float s2 = accH[mt][nt][2] + accL[mt][nt][2];
                float s3 = accH[mt][nt][3] + accL[mt][nt][3];
                int r1 = r0 + mbase + mt * 16 + g;
                int r2 = r1 + 8;
                int cc = nh * 64 + nbase + nt * 8 + tg * 2;
                if (r1 < nrows)
                    *reinterpret_cast<__half2*>(C + (size_t)r1 * 128 + cc) =
                        __floats2half2_rn(s0, s1);
                if (r2 < nrows)
                    *reinterpret_cast<__half2*>(C + (size_t)r2 * 128 + cc) =
                        __floats2half2_rn(s2, s3);
            }
        }
        __syncthreads();
    }
}

// ---------------- GEMM2: pre-split fp16 A planes, 2-pass, reg-prefetch -------
__global__ __launch_bounds__(256, 2)
void k_gemm_pre(const __half* __restrict__ Ahi, const __half* __restrict__ Alo,
                const __half* __restrict__ B, __half* __restrict__ C, int nrows) {
    constexpr int NCOL = 64;
    constexpr int WN = 16, NT = 2;
    constexpr int B_BYTES = NCOL * ROWB;
    constexpr int A_BYTES = 64 * ROWB;

    extern __shared__ char smem[];
    char* sB   = smem;
    char* sAhi = smem + B_BYTES;
    char* sAlo = sAhi + A_BYTES;

    const int tid = threadIdx.x;
    const int lane = tid & 31;
    const int wid = tid >> 5;
    const int g = lane >> 2;
    const int tg = lane & 3;
    const int mbase = (wid & 1) * 32;
    const int nbase = (wid >> 1) * WN;

    for (int i = tid; i < NCOL * 16; i += 256) {
        int n = i >> 4, q = i & 15;
        *reinterpret_cast<uint4*>(sB + n * ROWB + q * 16) =
            reinterpret_cast<const uint4*>(B + n * 128)[q];
    }

    const int rlm = lane & 7;
    const int qa = lane >> 3;
    uint32_t aAhi[2], aAlo[2];
#pragma unroll
    for (int mt = 0; mt < 2; mt++) {
        int row = mbase + mt * 16 + (qa & 1) * 8 + rlm;
        int col = (qa >> 1) * 16;
        aAhi[mt] = (uint32_t)__cvta_generic_to_shared(sAhi) + row * ROWB + col;
        aAlo[mt] = (uint32_t)__cvta_generic_to_shared(sAlo) + row * ROWB + col;
    }
    const int lb = lane & 15;
    uint32_t aB[NT];
#pragma unroll
    for (int nt = 0; nt < NT; nt++) {
        int row = nbase + nt * 8 + (lb & 7);
        int col = ((lb >> 3) & 1) * 16;
        aB[nt] = (uint32_t)__cvta_generic_to_shared(sB) + row * ROWB + col;
    }

    const int ntiles = (nrows + 63) / 64;
    const int half = tid >> 7;          // 0: hi plane, 1: lo plane
    const int m0 = (tid & 127) >> 4;
    const int q0 = tid & 15;
    const __half* Ap = half ? Alo : Ahi;
    char* sp = half ? sAlo : sAhi;

    // prologue
    uint4 v[8];
    {
        const int r0 = blockIdx.x * 64;
#pragma unroll
        for (int it = 0; it < 8; it++) {
            int gr = r0 + m0 + it * 8;
            v[it] = (gr < nrows && (int)blockIdx.x < ntiles)
                ? reinterpret_cast<const uint4*>(Ap + (size_t)gr * 128)[q0]
                : make_uint4(0u, 0u, 0u, 0u);
        }
    }

    for (int t = blockIdx.x; t < ntiles; t += gridDim.x) {
#pragma unroll
        for (int it = 0; it < 8; it++)
            *reinterpret_cast<uint4*>(sp + (m0 + it * 8) * ROWB + q0 * 16) = v[it];
        __syncthreads();

        const int tn = t + gridDim.x;
        if (tn < ntiles) {
            const int rn = tn * 64;
#pragma unroll
            for (int it = 0; it < 8; it++) {
                int gr = rn + m0 + it * 8;
                v[it] = (gr < nrows)
                    ? reinterpret_cast<const uint4*>(Ap + (size_t)gr * 128)[q0]
                    : make_uint4(0u, 0u, 0u, 0u);
            }
        }

        float accH[2][NT][4], accL[2][NT][4];
#pragma unroll
        for (int mt = 0; mt < 2; mt++)
#pragma unroll
            for (int nt = 0; nt < NT; nt++)
#pragma unroll
                for (int j = 0; j < 4; j++) {
                    accH[mt][nt][j] = 0.0f;
                    accL[mt][nt][j] = 0.0f;
                }

#pragma unroll
        for (int ks = 0; ks < 8; ks++) {
            const uint32_t ko = ks * 32;
            uint32_t ah[2][4], al[2][4];
#pragma unroll
            for (int mt = 0; mt < 2; mt++) {
                LDMX4(ah[mt][0], ah[mt][1], ah[mt][2], ah[mt][3], aAhi[mt] + ko);
                LDMX4(al[mt][0], al[mt][1], al[mt][2], al[mt][3], aAlo[mt] + ko);
            }
#pragma unroll
            for (int nt = 0; nt < NT; nt++) {
                uint32_t b0, b1;
                LDMX2(b0, b1, aB[nt] + ko);
#pragma unroll
                for (int mt = 0; mt < 2; mt++) {
                    MMA_F16(accH[mt][nt], ah[mt], b0, b1);
                    MMA_F16(accL[mt][nt], al[mt], b0, b1);
                }
            }
        }

        const int r0 = t * 64;
#pragma unroll
        for (int mt = 0; mt < 2; mt++) {
#pragma unroll
            for (int nt = 0; nt < NT; nt++) {
                float s0 = accH[mt][nt][0] + accL[mt][nt][0];
                float s1 = accH[mt][nt][1] + accL[mt][nt][1];
                float s2 = accH[mt][nt][2] + accL[mt][nt][2];
                float s3 = accH[mt][nt][3] + accL[mt][nt][3];
                int r1 = r0 + mbase + mt * 16 + g;
                int r2 = r1 + 8;
                int cc = nbase + nt * 8 + tg * 2;
                if (r1 < nrows)
                    *reinterpret_cast<__half2*>(C + (size_t)r1 * NCOL + cc) =
                        __floats2half2_rn(s0, s1);
                if (r2 < nrows)
                    *reinterpret_cast<__half2*>(C + (size_t)r2 * NCOL + cc) =
                        __floats2half2_rn(s2, s3);
            }
        }
        __syncthreads();
    }
}

// ---------------- agg1: mean + relu, fp16 in -> fp16 hi/lo out ---------------
__global__ void k_agg1(const __half* __restrict__ src,
                       __half* __restrict__ dhi, __half* __restrict__ dlo) {
    const int gw = (blockIdx.x * blockDim.x + threadIdx.x) >> 5;
    if (gw >= NN) return;
    const int lane = threadIdx.x & 31;

    const int d = g_deg[gw];
    const int cnt = d < CAP ? d : CAP;
    const int* __restrict__ adj = g_adj + (size_t)gw * CAP;

    float acc[4] = {0.f, 0.f, 0.f, 0.f};
#pragma unroll 4
    for (int t = 0; t < cnt; t++) {
        int j = __ldg(&adj[t]);
        uint2 v = *reinterpret_cast<const uint2*>(src + (size_t)j * 128 + lane * 4);
        float2 f0 = __half22float2(*reinterpret_cast<__half2*>(&v.x));
        float2 f1 = __half22float2(*reinterpret_cast<__half2*>(&v.y));
        acc[0] += f0.x; acc[1] += f0.y; acc[2] += f1.x; acc[3] += f1.y;
    }

    const float inv = 1.0f / (float)d;
    float o0 = fmaxf(acc[0] * inv, 0.f), o1 = fmaxf(acc[1] * inv, 0.f);
    float o2 = fmaxf(acc[2] * inv, 0.f), o3 = fmaxf(acc[3] * inv, 0.f);

    __half2 h01 = __float22half2_rn(make_float2(o0, o1));
    __half2 h23 = __float22half2_rn(make_float2(o2, o3));
    float2 f01 = __half22float2(h01);
    float2 f23 = __half22float2(h23);
    __half2 l01 = __float22half2_rn(make_float2(o0 - f01.x, o1 - f01.y));
    __half2 l23 = __float22half2_rn(make_float2(o2 - f23.x, o3 - f23.y));

    size_t off = (size_t)gw * 128 + lane * 4;
    *reinterpret_cast<uint2*>(dhi + off) = make_uint2(
        *reinterpret_cast<uint32_t*>(&h01), *reinterpret_cast<uint32_t*>(&h23));
    *reinterpret_cast<uint2*>(dlo + off) = make_uint2(
        *reinterpret_cast<uint32_t*>(&l01), *reinterpret_cast<uint32_t*>(&l23));
}

// ---------------- agg2: mean, fp16 in -> fp32 out -----------------------------
__global__ void k_agg2(const __half* __restrict__ src, float* __restrict__ dst) {
    const int gw = (blockIdx.x * blockDim.x + threadIdx.x) >> 5;
    if (gw >= NN) return;
    const int lane = threadIdx.x & 31;

    const int d = g_deg[gw];
    const int cnt = d < CAP ? d : CAP;
    const int* __restrict__ adj = g_adj + (size_t)gw * CAP;

    float acc0 = 0.f, acc1 = 0.f;
#pragma unroll 4
    for (int t = 0; t < cnt; t++) {
        int j = __ldg(&adj[t]);
        uint32_t v = *reinterpret_cast<const uint32_t*>(src + (size_t)j * 64 + lane * 2);
        float2 f = __half22float2(*reinterpret_cast<__half2*>(&v));
        acc0 += f.x; acc1 += f.y;
    }
    const float inv = 1.0f / (float)d;
    *reinterpret_cast<float2*>(dst + (size_t)gw * 64 + lane * 2) =
        make_float2(acc0 * inv, acc1 * inv);
}

// ---------------- launch --------------------------------------------------------
extern "C" void kernel_launch(void* const* d_in, const int* in_sizes, int n_in,
                              void* d_out, int out_size) {
    const float* x    = (const float*)d_in[0];
    const float* W1   = (const float*)d_in[1];
    const float* W2   = (const float*)d_in[2];
    const int*   erow = (const int*)d_in[3];
    const int*   ecol = (const int*)d_in[4];
    float* out = (float*)d_out;

    __half *h0, *h2, *h1hi, *h1lo, *w1, *w2;
    cudaGetSymbolAddress((void**)&h0,   g_h0);
    cudaGetSymbolAddress((void**)&h1hi, g_h1hi);
    cudaGetSymbolAddress((void**)&h1lo, g_h1lo);
    cudaGetSymbolAddress((void**)&h2,   g_h2);
    cudaGetSymbolAddress((void**)&w1,   g_w1);
    cudaGetSymbolAddress((void**)&w2,   g_w2);

    const int SMEM = 3 * 64 * ROWB;   // 52224 (B + A hi + A lo)
    cudaFuncSetAttribute(k_gemm_conv, cudaFuncAttributeMaxDynamicSharedMemorySize, SMEM);
    cudaFuncSetAttribute(k_gemm_pre,  cudaFuncAttributeMaxDynamicSharedMemorySize, SMEM);

    // fork a side stream so build_adj overlaps prep + gemm1
    cudaStream_t s2;
    cudaStreamCreateWithFlags(&s2, cudaStreamNonBlocking);
    cudaEvent_t evFork, evJoin;
    cudaEventCreateWithFlags(&evFork, cudaEventDisableTiming);
    cudaEventCreateWithFlags(&evJoin, cudaEventDisableTiming);

    k_prep_w1<<<(NN + 255) / 256, 256>>>(W1, w1);                                 // 1
    cudaEventRecord(evFork, 0);
    cudaStreamWaitEvent(s2, evFork, 0);
    k_build_adj<<<(EE / 4 + 255) / 256, 256, 0, s2>>>(erow, ecol);                // 2 (side)
    cudaEventRecord(evJoin, s2);

    k_prep_w2<<<(128 * 64 + 255) / 256, 256>>>(W2, w2);                           // 3
    k_gemm_conv<<<2 * NSM, 256, SMEM>>>(x, w1, h0, NN);                           // 4 (slot 4)

    cudaStreamWaitEvent(0, evJoin, 0);   // adjacency ready before agg1
    k_agg1<<<(NN * 32 + 255) / 256, 256>>>(h0, h1hi, h1lo);                       // 5
    k_gemm_pre<<<2 * NSM, 256, SMEM>>>(h1hi, h1lo, w2, h2, NN);                   // 6
    k_agg2<<<(NN * 32 + 255) / 256, 256>>>(h2, out);                              // 7

    cudaEventDestroy(evFork);
    cudaEventDestroy(evJoin);
    cudaStreamDestroy(s2);
}

// round 12
// speedup vs baseline: 1.1945x; 1.0571x over previous
#include <cuda_runtime.h>
#include <cuda_bf16.h>
#include <cuda_fp16.h>
#include <cstdint>

// Problem constants (fixed by the dataset)
#define NN   100000      // nodes
#define EE   1600000     // edges
#define CAP  128         // adjacency bucket capacity per node
#define NSM  152         // GB300 SM count

// ---------------- scratch (device globals; no allocation allowed) ----------
__device__ __half  g_h0[(size_t)NN * 128];   // x @ W1 (fp16)
__device__ __half  g_h1[(size_t)NN * 128];   // relu(agg h0) (fp16, single plane)
__device__ __half  g_h2[(size_t)NN * 64];    // h1 @ W2 (fp16)
__device__ int     g_deg[NN];
__device__ int     g_adj[(size_t)NN * CAP];
__device__ __half  g_w1[128 * 128];          // W1^T, fp16
__device__ __half  g_w2[64 * 128];           // W2^T, fp16

#define ROWB 272   // smem row pitch: 128 halves (256B) + 16B pad, ldmatrix conflict-free

// ---------------- prep 1: clear degrees + W1 transpose -> fp16 ---------------
__global__ void k_prep_w1(const float* __restrict__ W1, __half* __restrict__ w1) {
    int i = blockIdx.x * blockDim.x + threadIdx.x;
    if (i < NN) g_deg[i] = 0;
    if (i < 128 * 128) {
        int k = i / 128, n = i % 128;
        w1[n * 128 + k] = __float2half_rn(W1[i]);
    }
}

// ---------------- prep 2: W2 transpose -> fp16 --------------------------------
__global__ void k_prep_w2(const float* __restrict__ W2, __half* __restrict__ w2) {
    int i = blockIdx.x * blockDim.x + threadIdx.x;
    if (i < 128 * 64) {
        int k = i / 64, n = i % 64;
        w2[n * 128 + k] = __float2half_rn(W2[i]);
    }
}

// ---------------- adjacency build: 4 edges/thread ---------------------------
__global__ void k_build_adj(const int* __restrict__ erow,
                            const int* __restrict__ ecol) {
    int e0 = (blockIdx.x * blockDim.x + threadIdx.x) * 4;
    if (e0 >= EE) return;
    int4 r = *reinterpret_cast<const int4*>(erow + e0);
    int4 c = *reinterpret_cast<const int4*>(ecol + e0);
    int p0 = atomicAdd(&g_deg[r.x], 1);
    int p1 = atomicAdd(&g_deg[r.y], 1);
    int p2 = atomicAdd(&g_deg[r.z], 1);
    int p3 = atomicAdd(&g_deg[r.w], 1);
    if (p0 < CAP) g_adj[(size_t)r.x * CAP + p0] = c.x;
    if (p1 < CAP) g_adj[(size_t)r.y * CAP + p1] = c.y;
    if (p2 < CAP) g_adj[(size_t)r.z * CAP + p2] = c.z;
    if (p3 < CAP) g_adj[(size_t)r.w * CAP + p3] = c.w;
}

// ---------------- mma / ldmatrix helpers -------------------------------------
#define LDMX4(r0, r1, r2, r3, addr) \
    asm volatile("ldmatrix.sync.aligned.m8n8.x4.shared.b16 {%0,%1,%2,%3}, [%4];" \
                 : "=r"(r0), "=r"(r1), "=r"(r2), "=r"(r3) : "r"(addr))
#define LDMX2(r0, r1, addr) \
    asm volatile("ldmatrix.sync.aligned.m8n8.x2.shared.b16 {%0,%1}, [%2];" \
                 : "=r"(r0), "=r"(r1) : "r"(addr))
#define MMA_F16(acc, a, b0, b1) \
    asm volatile("mma.sync.aligned.m16n8k16.row.col.f32.f16.f16.f32 " \
                 "{%0,%1,%2,%3}, {%4,%5,%6,%7}, {%8,%9}, {%0,%1,%2,%3};" \
                 : "+f"(acc[0]), "+f"(acc[1]), "+f"(acc[2]), "+f"(acc[3]) \
                 : "r"(a[0]), "r"(a[1]), "r"(a[2]), "r"(a[3]), "r"(b0), "r"(b1))

// ---------------- GEMM1: fp32 A -> fp16 hi/lo 2-pass, reg-prefetch -----------
// (unchanged from R11 — proven at 34.7 us)
__global__ __launch_bounds__(256, 2)
void k_gemm_conv(const float* __restrict__ A, const __half* __restrict__ B,
                 __half* __restrict__ C, int nrows) {
    constexpr int NC = 64;
    constexpr int WN = 16, NT = 2;
    constexpr int B_BYTES = NC * ROWB;
    constexpr int A_BYTES = 64 * ROWB;

    extern __shared__ char smem[];
    char* sB   = smem;
    char* sAhi = smem + B_BYTES;
    char* sAlo = sAhi + A_BYTES;

    const int nh = blockIdx.x & 1;
    const int cta = blockIdx.x >> 1;
    const int nctas = gridDim.x >> 1;

    const int tid = threadIdx.x;
    const int lane = tid & 31;
    const int wid = tid >> 5;
    const int g = lane >> 2;
    const int tg = lane & 3;
    const int mbase = (wid & 1) * 32;
    const int nbase = (wid >> 1) * WN;

    const __half* Bp = B + nh * 64 * 128;

    for (int i = tid; i < NC * 16; i += 256) {
        int n = i >> 4, q = i & 15;
        *reinterpret_cast<uint4*>(sB + n * ROWB + q * 16) =
            reinterpret_cast<const uint4*>(Bp + n * 128)[q];
    }

    const int rlm = lane & 7;
    const int qa = lane >> 3;
    uint32_t aAhi[2], aAlo[2];
#pragma unroll
    for (int mt = 0; mt < 2; mt++) {
        int row = mbase + mt * 16 + (qa & 1) * 8 + rlm;
        int col = (qa >> 1) * 16;
        aAhi[mt] = (uint32_t)__cvta_generic_to_shared(sAhi) + row * ROWB + col;
        aAlo[mt] = (uint32_t)__cvta_generic_to_shared(sAlo) + row * ROWB + col;
    }
    const int lb = lane & 15;
    uint32_t aB[NT];
#pragma unroll
    for (int nt = 0; nt < NT; nt++) {
        int row = nbase + nt * 8 + (lb & 7);
        int col = ((lb >> 3) & 1) * 16;
        aB[nt] = (uint32_t)__cvta_generic_to_shared(sB) + row * ROWB + col;
    }

    const int ntiles = (nrows + 63) / 64;
    const int m0 = tid >> 5;
    const int q0 = tid & 31;

    float4 v[8];
    {
        const int r0 = cta * 64;
#pragma unroll
        for (int it = 0; it < 8; it++) {
            int gr = r0 + m0 + it * 8;
            v[it] = (gr < nrows && cta < ntiles)
                ? *reinterpret_cast<const float4*>(A + (size_t)gr * 128 + q0 * 4)
                : make_float4(0.f, 0.f, 0.f, 0.f);
        }
    }

    for (int t = cta; t < ntiles; t += nctas) {
#pragma unroll
        for (int it = 0; it < 8; it++) {
            int m = m0 + it * 8;
            __half2 h01 = __float22half2_rn(make_float2(v[it].x, v[it].y));
            __half2 h23 = __float22half2_rn(make_float2(v[it].z, v[it].w));
            float2 f01 = __half22float2(h01);
            float2 f23 = __half22float2(h23);
            __half2 l01 = __float22half2_rn(make_float2(v[it].x - f01.x, v[it].y - f01.y));
            __half2 l23 = __float22half2_rn(make_float2(v[it].z - f23.x, v[it].w - f23.y));
            *reinterpret_cast<uint2*>(sAhi + m * ROWB + q0 * 8) = make_uint2(
                *reinterpret_cast<uint32_t*>(&h01), *reinterpret_cast<uint32_t*>(&h23));
            *reinterpret_cast<uint2*>(sAlo + m * ROWB + q0 * 8) = make_uint2(
                *reinterpret_cast<uint32_t*>(&l01), *reinterpret_cast<uint32_t*>(&l23));
        }
        __syncthreads();

        const int tn = t + nctas;
        if (tn < ntiles) {
            const int rn = tn * 64;
#pragma unroll
            for (int it = 0; it < 8; it++) {
                int gr = rn + m0 + it * 8;
                v[it] = (gr < nrows)
                    ? *reinterpret_cast<const float4*>(A + (size_t)gr * 128 + q0 * 4)
                    : make_float4(0.f, 0.f, 0.f, 0.f);
            }
        }

        float accH[2][NT][4], accL[2][NT][4];
#pragma unroll
        for (int mt = 0; mt < 2; mt++)
#pragma unroll
            for (int nt = 0; nt < NT; nt++)
#pragma unroll
                for (int j = 0; j < 4; j++) {
                    accH[mt][nt][j] = 0.0f;
                    accL[mt][nt][j] = 0.0f;
                }

#pragma unroll
        for (int ks = 0; ks < 8; ks++) {
            const uint32_t ko = ks * 32;
            uint32_t ah[2][4], al[2][4];
#pragma unroll
            for (int mt = 0; mt < 2; mt++) {
                LDMX4(ah[mt][0], ah[mt][1], ah[mt][2], ah[mt][3], aAhi[mt] + ko);
                LDMX4(al[mt][0], al[mt][1], al[mt][2], al[mt][3], aAlo[mt] + ko);
            }
#pragma unroll
            for (int nt = 0; nt < NT; nt++) {
                uint32_t b0, b1;
                LDMX2(b0, b1, aB[nt] + ko);
#pragma unroll
                for (int mt = 0; mt < 2; mt++) {
                    MMA_F16(accH[mt][nt], ah[mt], b0, b1);
                    MMA_F16(accL[mt][nt], al[mt], b0, b1);
                }
            }
        }

        const int r0 = t * 64;
#pragma unroll
        for (int mt = 0; mt < 2; mt++) {
#pragma unroll
            for (int nt = 0; nt < NT; nt++) {
                float s0 = accH[mt][nt][0] + accL[mt][nt][0];
                float s1 = accH[mt][nt][1] + accL[mt][nt][1];
                float s2 = accH[mt][nt][2] + accL[mt][nt][2];
                float s3 = accH[mt][nt][3] + accL[mt][nt][3];
                int r1 = r0 + mbase + mt * 16 + g;
                int r2 = r1 + 8;
                int cc = nh * 64 + nbase + nt * 8 + tg * 2;
                if (r1 < nrows)
                    *reinterpret_cast<__half2*>(C + (size_t)r1 * 128 + cc) =
                        __floats2half2_rn(s0, s1);
                if (r2 < nrows)
                    *reinterpret_cast<__half2*>(C + (size_t)r2 * 128 + cc) =
                        __floats2half2_rn(s2, s3);
            }
        }
        __syncthreads();
    }
}

// ---------------- GEMM2: single fp16 A plane, single-pass, reg-prefetch ------
// C[nrows,64](fp16) = A[nrows,128](fp16) @ W2. 8 warps = 2M x 4N, 64-row tiles.
__global__ __launch_bounds__(256, 3)
void k_gemm2(const __half* __restrict__ A, const __half* __restrict__ B,
             __half* __restrict__ C, int nrows) {
    constexpr int NCOL = 64;
    constexpr int WN = 16, NT = 2;
    constexpr int B_BYTES = NCOL * ROWB;

    extern __shared__ char smem[];
    char* sB = smem;
    char* sA = smem + B_BYTES;

    const int tid = threadIdx.x;
    const int lane = tid & 31;
    const int wid = tid >> 5;
    const int g = lane >> 2;
    const int tg = lane & 3;
    const int mbase = (wid & 1) * 32;
    const int nbase = (wid >> 1) * WN;

    for (int i = tid; i < NCOL * 16; i += 256) {
        int n = i >> 4, q = i & 15;
        *reinterpret_cast<uint4*>(sB + n * ROWB + q * 16) =
            reinterpret_cast<const uint4*>(B + n * 128)[q];
    }

    const int rlm = lane & 7;
    const int qa = lane >> 3;
    uint32_t aA[2];
#pragma unroll
    for (int mt = 0; mt < 2; mt++) {
        int row = mbase + mt * 16 + (qa & 1) * 8 + rlm;
        int col = (qa >> 1) * 16;
        aA[mt] = (uint32_t)__cvta_generic_to_shared(sA) + row * ROWB + col;
    }
    const int lb = lane & 15;
    uint32_t aB[NT];
#pragma unroll
    for (int nt = 0; nt < NT; nt++) {
        int row = nbase + nt * 8 + (lb & 7);
        int col = ((lb >> 3) & 1) * 16;
        aB[nt] = (uint32_t)__cvta_generic_to_shared(sB) + row * ROWB + col;
    }

    const int ntiles = (nrows + 63) / 64;
    const int m0 = tid >> 4;          // rows m0, m0+16, m0+32, m0+48
    const int q0 = tid & 15;          // uint4 column (16 per row)

    // prologue: 64 rows x 16 uint4 = 1024 chunks, 4/thread
    uint4 v[4];
    {
        const int r0 = blockIdx.x * 64;
#pragma unroll
        for (int it = 0; it < 4; it++) {
            int gr = r0 + m0 + it * 16;
            v[it] = (gr < nrows && (int)blockIdx.x < ntiles)
                ? reinterpret_cast<const uint4*>(A + (size_t)gr * 128)[q0]
                : make_uint4(0u, 0u, 0u, 0u);
        }
    }

    for (int t = blockIdx.x; t < ntiles; t += gridDim.x) {
#pragma unroll
        for (int it = 0; it < 4; it++)
            *reinterpret_cast<uint4*>(sA + (m0 + it * 16) * ROWB + q0 * 16) = v[it];
        __syncthreads();

        const int tn = t + gridDim.x;
        if (tn < ntiles) {
            const int rn = tn * 64;
#pragma unroll
            for (int it = 0; it < 4; it++) {
                int gr = rn + m0 + it * 16;
                v[it] = (gr < nrows)
                    ? reinterpret_cast<const uint4*>(A + (size_t)gr * 128)[q0]
                    : make_uint4(0u, 0u, 0u, 0u);
            }
        }

        float acc[2][NT][4];
#pragma unroll
        for (int mt = 0; mt < 2; mt++)
#pragma unroll
            for (int nt = 0; nt < NT; nt++)
#pragma unroll
                for (int j = 0; j < 4; j++) acc[mt][nt][j] = 0.0f;

#pragma unroll
        for (int ks = 0; ks < 8; ks++) {
            const uint32_t ko = ks * 32;
            uint32_t a[2][4];
#pragma unroll
            for (int mt = 0; mt < 2; mt++)
                LDMX4(a[mt][0], a[mt][1], a[mt][2], a[mt][3], aA[mt] + ko);
#pragma unroll
            for (int nt = 0; nt < NT; nt++) {
                uint32_t b0, b1;
                LDMX2(b0, b1, aB[nt] + ko);
#pragma unroll
                for (int mt = 0; mt < 2; mt++)
                    MMA_F16(acc[mt][nt], a[mt], b0, b1);
            }
        }

        const int r0 = t * 64;
#pragma unroll
        for (int mt = 0; mt < 2; mt++) {
#pragma unroll
            for (int nt = 0; nt < NT; nt++) {
                int r1 = r0 + mbase + mt * 16 + g;
                int r2 = r1 + 8;
                int cc = nbase + nt * 8 + tg * 2;
                if (r1 < nrows)
                    *reinterpret_cast<__half2*>(C + (size_t)r1 * NCOL + cc) =
                        __floats2half2_rn(acc[mt][nt][0], acc[mt][nt][1]);
                if (r2 < nrows)
                    *reinterpret_cast<__half2*>(C + (size_t)r2 * NCOL + cc) =
                        __floats2half2_rn(acc[mt][nt][2], acc[mt][nt][3]);
            }
        }
        __syncthreads();
    }
}

// ---------------- agg1: mean + relu, fp16 in -> single fp16 plane out --------
__global__ void k_agg1(const __half* __restrict__ src, __half* __restrict__ dst) {
    const int gw = (blockIdx.x * blockDim.x + threadIdx.x) >> 5;
    if (gw >= NN) return;
    const int lane = threadIdx.x & 31;

    const int d = g_deg[gw];
    const int cnt = d < CAP ? d : CAP;
    const int* __restrict__ adj = g_adj + (size_t)gw * CAP;

    float acc[4] = {0.f, 0.f, 0.f, 0.f};
#pragma unroll 4
    for (int t = 0; t < cnt; t++) {
        int j = __ldg(&adj[t]);
        uint2 v = *reinterpret_cast<const uint2*>(src + (size_t)j * 128 + lane * 4);
        float2 f0 = __half22float2(*reinterpret_cast<__half2*>(&v.x));
        float2 f1 = __half22float2(*reinterpret_cast<__half2*>(&v.y));
        acc[0] += f0.x; acc[1] += f0.y; acc[2] += f1.x; acc[3] += f1.y;
    }

    const float inv = 1.0f / (float)d;
    float o0 = fmaxf(acc[0] * inv, 0.f), o1 = fmaxf(acc[1] * inv, 0.f);
    float o2 = fmaxf(acc[2] * inv, 0.f), o3 = fmaxf(acc[3] * inv, 0.f);

    __half2 h01 = __float22half2_rn(make_float2(o0, o1));
    __half2 h23 = __float22half2_rn(make_float2(o2, o3));
    *reinterpret_cast<uint2*>(dst + (size_t)gw * 128 + lane * 4) = make_uint2(
        *reinterpret_cast<uint32_t*>(&h01), *reinterpret_cast<uint32_t*>(&h23));
}

// ---------------- agg2: mean, fp16 in -> fp32 out -----------------------------
__global__ void k_agg2(const __half* __restrict__ src, float* __restrict__ dst) {
    const int gw = (blockIdx.x * blockDim.x + threadIdx.x) >> 5;
    if (gw >= NN) return;
    const int lane = threadIdx.x & 31;

    const int d = g_deg[gw];
    const int cnt = d < CAP ? d : CAP;
    const int* __restrict__ adj = g_adj + (size_t)gw * CAP;

    float acc0 = 0.f, acc1 = 0.f;
#pragma unroll 4
    for (int t = 0; t < cnt; t++) {
        int j = __ldg(&adj[t]);
        uint32_t v = *reinterpret_cast<const uint32_t*>(src + (size_t)j * 64 + lane * 2);
        float2 f = __half22float2(*reinterpret_cast<__half2*>(&v));
        acc0 += f.x; acc1 += f.y;
    }
    const float inv = 1.0f / (float)d;
    *reinterpret_cast<float2*>(dst + (size_t)gw * 64 + lane * 2) =
        make_float2(acc0 * inv, acc1 * inv);
}

// ---------------- launch --------------------------------------------------------
extern "C" void kernel_launch(void* const* d_in, const int* in_sizes, int n_in,
                              void* d_out, int out_size) {
    const float* x    = (const float*)d_in[0];
    const float* W1   = (const float*)d_in[1];
    const float* W2   = (const float*)d_in[2];
    const int*   erow = (const int*)d_in[3];
    const int*   ecol = (const int*)d_in[4];
    float* out = (float*)d_out;

    __half *h0, *h1, *h2, *w1, *w2;
    cudaGetSymbolAddress((void**)&h0, g_h0);
    cudaGetSymbolAddress((void**)&h1, g_h1);
    cudaGetSymbolAddress((void**)&h2, g_h2);
    cudaGetSymbolAddress((void**)&w1, g_w1);
    cudaGetSymbolAddress((void**)&w2, g_w2);

    const int SMEM1 = 3 * 64 * ROWB;   // 52224 (B + A hi + A lo)
    const int SMEM2 = 2 * 64 * ROWB;   // 34816 (B + A)
    cudaFuncSetAttribute(k_gemm_conv, cudaFuncAttributeMaxDynamicSharedMemorySize, SMEM1);
    cudaFuncSetAttribute(k_gemm2,     cudaFuncAttributeMaxDynamicSharedMemorySize, SMEM2);

    // fork a side stream so build_adj overlaps prep + gemm1
    cudaStream_t s2;
    cudaStreamCreateWithFlags(&s2, cudaStreamNonBlocking);
    cudaEvent_t evFork, evJoin;
    cudaEventCreateWithFlags(&evFork, cudaEventDisableTiming);
    cudaEventCreateWithFlags(&evJoin, cudaEventDisableTiming);

    k_prep_w1<<<(NN + 255) / 256, 256>>>(W1, w1);                                 // 1
    cudaEventRecord(evFork, 0);
    cudaStreamWaitEvent(s2, evFork, 0);
    k_build_adj<<<(EE / 4 + 255) / 256, 256, 0, s2>>>(erow, ecol);                // 2 (side)
    cudaEventRecord(evJoin, s2);

    k_gemm_conv<<<2 * NSM, 256, SMEM1>>>(x, w1, h0, NN);                          // 3

    cudaStreamWaitEvent(0, evJoin, 0);   // adjacency ready before agg1
    k_agg1<<<(NN * 32 + 255) / 256, 256>>>(h0, h1);                               // 4 (slot 4)
    k_prep_w2<<<(128 * 64 + 255) / 256, 256>>>(W2, w2);                           // 5
    k_gemm2<<<3 * NSM, 256, SMEM2>>>(h1, w2, h2, NN);                             // 6
    k_agg2<<<(NN * 32 + 255) / 256, 256>>>(h2, out);                              // 7

    cudaEventDestroy(evFork);
    cudaEventDestroy(evJoin);
    cudaStreamDestroy(s2);
}

// round 13
// speedup vs baseline: 1.2137x; 1.0160x over previous
#include <cuda_runtime.h>
#include <cuda_bf16.h>
#include <cuda_fp16.h>
#include <cstdint>

// Problem constants (fixed by the dataset)
#define NN   100000      // nodes
#define EE   1600000     // edges
#define CAP  128         // adjacency bucket capacity per node
#define NSM  152         // GB300 SM count

// ---------------- scratch (device globals; no allocation allowed) ----------
__device__ __half  g_h0[(size_t)NN * 128];   // x @ W1 (fp16)
__device__ __half  g_h1[(size_t)NN * 128];   // relu(agg h0) (fp16)
__device__ __half  g_h2[(size_t)NN * 64];    // h1 @ W2 (fp16)
__device__ int     g_deg[NN];
__device__ int     g_adj[(size_t)NN * CAP];
__device__ __half  g_w1[128 * 128];          // W1^T, fp16
__device__ __half  g_w2[64 * 128];           // W2^T, fp16

#define ROWB 272   // smem row pitch: 128 halves (256B) + 16B pad, ldmatrix conflict-free

// ---------------- prep 1: clear degrees + W1 transpose -> fp16 ---------------
__global__ void k_prep_w1(const float* __restrict__ W1, __half* __restrict__ w1) {
    int i = blockIdx.x * blockDim.x + threadIdx.x;
    if (i < NN) g_deg[i] = 0;
    if (i < 128 * 128) {
        int k = i / 128, n = i % 128;
        w1[n * 128 + k] = __float2half_rn(W1[i]);
    }
}

// ---------------- prep 2: W2 transpose -> fp16 --------------------------------
__global__ void k_prep_w2(const float* __restrict__ W2, __half* __restrict__ w2) {
    int i = blockIdx.x * blockDim.x + threadIdx.x;
    if (i < 128 * 64) {
        int k = i / 64, n = i % 64;
        w2[n * 128 + k] = __float2half_rn(W2[i]);
    }
}

// ---------------- adjacency build: 4 edges/thread ---------------------------
__global__ void k_build_adj(const int* __restrict__ erow,
                            const int* __restrict__ ecol) {
    int e0 = (blockIdx.x * blockDim.x + threadIdx.x) * 4;
    if (e0 >= EE) return;
    int4 r = *reinterpret_cast<const int4*>(erow + e0);
    int4 c = *reinterpret_cast<const int4*>(ecol + e0);
    int p0 = atomicAdd(&g_deg[r.x], 1);
    int p1 = atomicAdd(&g_deg[r.y], 1);
    int p2 = atomicAdd(&g_deg[r.z], 1);
    int p3 = atomicAdd(&g_deg[r.w], 1);
    if (p0 < CAP) g_adj[(size_t)r.x * CAP + p0] = c.x;
    if (p1 < CAP) g_adj[(size_t)r.y * CAP + p1] = c.y;
    if (p2 < CAP) g_adj[(size_t)r.z * CAP + p2] = c.z;
    if (p3 < CAP) g_adj[(size_t)r.w * CAP + p3] = c.w;
}

// ---------------- mma / ldmatrix helpers -------------------------------------
#define LDMX4(r0, r1, r2, r3, addr) \
    asm volatile("ldmatrix.sync.aligned.m8n8.x4.shared.b16 {%0,%1,%2,%3}, [%4];" \
                 : "=r"(r0), "=r"(r1), "=r"(r2), "=r"(r3) : "r"(addr))
#define LDMX2(r0, r1, addr) \
    asm volatile("ldmatrix.sync.aligned.m8n8.x2.shared.b16 {%0,%1}, [%2];" \
                 : "=r"(r0), "=r"(r1) : "r"(addr))
#define MMA_F16(acc, a, b0, b1) \
    asm volatile("mma.sync.aligned.m16n8k16.row.col.f32.f16.f16.f32 " \
                 "{%0,%1,%2,%3}, {%4,%5,%6,%7}, {%8,%9}, {%0,%1,%2,%3};" \
                 : "+f"(acc[0]), "+f"(acc[1]), "+f"(acc[2]), "+f"(acc[3]) \
                 : "r"(a[0]), "r"(a[1]), "r"(a[2]), "r"(a[3]), "r"(b0), "r"(b1))

// ---------------- GEMM1: fp32 A -> fp16 single-pass, reg-prefetch ------------
// Output C[nrows,128](fp16). CTA tile 64 rows x 64 cols (nh = blockIdx.x & 1).
__global__ __launch_bounds__(256, 3)
void k_gemm1(const float* __restrict__ A, const __half* __restrict__ B,
             __half* __restrict__ C, int nrows) {
    constexpr int NC = 64;
    constexpr int WN = 16, NT = 2;
    constexpr int B_BYTES = NC * ROWB;

    extern __shared__ char smem[];
    char* sB = smem;
    char* sA = smem + B_BYTES;

    const int nh = blockIdx.x & 1;
    const int cta = blockIdx.x >> 1;
    const int nctas = gridDim.x >> 1;

    const int tid = threadIdx.x;
    const int lane = tid & 31;
    const int wid = tid >> 5;
    const int g = lane >> 2;
    const int tg = lane & 3;
    const int mbase = (wid & 1) * 32;
    const int nbase = (wid >> 1) * WN;

    const __half* Bp = B + nh * 64 * 128;

    // stage B once (64 rows x 16 uint4)
    for (int i = tid; i < NC * 16; i += 256) {
        int n = i >> 4, q = i & 15;
        *reinterpret_cast<uint4*>(sB + n * ROWB + q * 16) =
            reinterpret_cast<const uint4*>(Bp + n * 128)[q];
    }

    // ldmatrix base addresses
    const int rlm = lane & 7;
    const int qa = lane >> 3;
    uint32_t aA[2];
#pragma unroll
    for (int mt = 0; mt < 2; mt++) {
        int row = mbase + mt * 16 + (qa & 1) * 8 + rlm;
        int col = (qa >> 1) * 16;
        aA[mt] = (uint32_t)__cvta_generic_to_shared(sA) + row * ROWB + col;
    }
    const int lb = lane & 15;
    uint32_t aB[NT];
#pragma unroll
    for (int nt = 0; nt < NT; nt++) {
        int row = nbase + nt * 8 + (lb & 7);
        int col = ((lb >> 3) & 1) * 16;
        aB[nt] = (uint32_t)__cvta_generic_to_shared(sB) + row * ROWB + col;
    }

    const int ntiles = (nrows + 63) / 64;
    const int m0 = tid >> 5;    // rows m0, m0+8, ..., m0+56
    const int q0 = tid & 31;    // float4 column

    // prologue: load first tile into registers
    float4 v[8];
    {
        const int r0 = cta * 64;
#pragma unroll
        for (int it = 0; it < 8; it++) {
            int gr = r0 + m0 + it * 8;
            v[it] = (gr < nrows && cta < ntiles)
                ? *reinterpret_cast<const float4*>(A + (size_t)gr * 128 + q0 * 4)
                : make_float4(0.f, 0.f, 0.f, 0.f);
        }
    }

    for (int t = cta; t < ntiles; t += nctas) {
        // convert + store registers -> smem (single fp16 plane)
#pragma unroll
        for (int it = 0; it < 8; it++) {
            int m = m0 + it * 8;
            __half2 h01 = __float22half2_rn(make_float2(v[it].x, v[it].y));
            __half2 h23 = __float22half2_rn(make_float2(v[it].z, v[it].w));
            *reinterpret_cast<uint2*>(sA + m * ROWB + q0 * 8) = make_uint2(
                *reinterpret_cast<uint32_t*>(&h01), *reinterpret_cast<uint32_t*>(&h23));
        }
        __syncthreads();

        // prefetch next tile — lands during the MMA phase
        const int tn = t + nctas;
        if (tn < ntiles) {
            const int rn = tn * 64;
#pragma unroll
            for (int it = 0; it < 8; it++) {
                int gr = rn + m0 + it * 8;
                v[it] = (gr < nrows)
                    ? *reinterpret_cast<const float4*>(A + (size_t)gr * 128 + q0 * 4)
                    : make_float4(0.f, 0.f, 0.f, 0.f);
            }
        }

        float acc[2][NT][4];
#pragma unroll
        for (int mt = 0; mt < 2; mt++)
#pragma unroll
            for (int nt = 0; nt < NT; nt++)
#pragma unroll
                for (int j = 0; j < 4; j++) acc[mt][nt][j] = 0.0f;

#pragma unroll
        for (int ks = 0; ks < 8; ks++) {
            const uint32_t ko = ks * 32;
            uint32_t a[2][4];
#pragma unroll
            for (int mt = 0; mt < 2; mt++)
                LDMX4(a[mt][0], a[mt][1], a[mt][2], a[mt][3], aA[mt] + ko);
#pragma unroll
            for (int nt = 0; nt < NT; nt++) {
                uint32_t b0, b1;
                LDMX2(b0, b1, aB[nt] + ko);
#pragma unroll
                for (int mt = 0; mt < 2; mt++)
                    MMA_F16(acc[mt][nt], a[mt], b0, b1);
            }
        }

        const int r0 = t * 64;
#pragma unroll
        for (int mt = 0; mt < 2; mt++) {
#pragma unroll
            for (int nt = 0; nt < NT; nt++) {
                int r1 = r0 + mbase + mt * 16 + g;
                int r2 = r1 + 8;
                int cc = nh * 64 + nbase + nt * 8 + tg * 2;
                if (r1 < nrows)
                    *reinterpret_cast<__half2*>(C + (size_t)r1 * 128 + cc) =
                        __floats2half2_rn(acc[mt][nt][0], acc[mt][nt][1]);
                if (r2 < nrows)
                    *reinterpret_cast<__half2*>(C + (size_t)r2 * 128 + cc) =
                        __floats2half2_rn(acc[mt][nt][2], acc[mt][nt][3]);
            }
        }
        __syncthreads();
    }
}

// ---------------- GEMM2: single fp16 A plane, single-pass (unchanged R12) ----
__global__ __launch_bounds__(256, 3)
void k_gemm2(const __half* __restrict__ A, const __half* __restrict__ B,
             __half* __restrict__ C, int nrows) {
    constexpr int NCOL = 64;
    constexpr int WN = 16, NT = 2;
    constexpr int B_BYTES = NCOL * ROWB;

    extern __shared__ char smem[];
    char* sB = smem;
    char* sA = smem + B_BYTES;

    const int tid = threadIdx.x;
    const int lane = tid & 31;
    const int wid = tid >> 5;
    const int g = lane >> 2;
    const int tg = lane & 3;
    const int mbase = (wid & 1) * 32;
    const int nbase = (wid >> 1) * WN;

    for (int i = tid; i < NCOL * 16; i += 256) {
        int n = i >> 4, q = i & 15;
        *reinterpret_cast<uint4*>(sB + n * ROWB + q * 16) =
            reinterpret_cast<const uint4*>(B + n * 128)[q];
    }

    const int rlm = lane & 7;
    const int qa = lane >> 3;
    uint32_t aA[2];
#pragma unroll
    for (int mt = 0; mt < 2; mt++) {
        int row = mbase + mt * 16 + (qa & 1) * 8 + rlm;
        int col = (qa >> 1) * 16;
        aA[mt] = (uint32_t)__cvta_generic_to_shared(sA) + row * ROWB + col;
    }
    const int lb = lane & 15;
    uint32_t aB[NT];
#pragma unroll
    for (int nt = 0; nt < NT; nt++) {
        int row = nbase + nt * 8 + (lb & 7);
        int col = ((lb >> 3) & 1) * 16;
        aB[nt] = (uint32_t)__cvta_generic_to_shared(sB) + row * ROWB + col;
    }

    const int ntiles = (nrows + 63) / 64;
    const int m0 = tid >> 4;
    const int q0 = tid & 15;

    uint4 v[4];
    {
        const int r0 = blockIdx.x * 64;
#pragma unroll
        for (int it = 0; it < 4; it++) {
            int gr = r0 + m0 + it * 16;
            v[it] = (gr < nrows && (int)blockIdx.x < ntiles)
                ? reinterpret_cast<const uint4*>(A + (size_t)gr * 128)[q0]
                : make_uint4(0u, 0u, 0u, 0u);
        }
    }

    for (int t = blockIdx.x; t < ntiles; t += gridDim.x) {
#pragma unroll
        for (int it = 0; it < 4; it++)
            *reinterpret_cast<uint4*>(sA + (m0 + it * 16) * ROWB + q0 * 16) = v[it];
        __syncthreads();

        const int tn = t + gridDim.x;
        if (tn < ntiles) {
            const int rn = tn * 64;
#pragma unroll
            for (int it = 0; it < 4; it++) {
                int gr = rn + m0 + it * 16;
                v[it] = (gr < nrows)
                    ? reinterpret_cast<const uint4*>(A + (size_t)gr * 128)[q0]
                    : make_uint4(0u, 0u, 0u, 0u);
            }
        }

        float acc[2][NT][4];
#pragma unroll
        for (int mt = 0; mt < 2; mt++)
#pragma unroll
            for (int nt = 0; nt < NT; nt++)
#pragma unroll
                for (int j = 0; j < 4; j++) acc[mt][nt][j] = 0.0f;

#pragma unroll
        for (int ks = 0; ks < 8; ks++) {
            const uint32_t ko = ks * 32;
            uint32_t a[2][4];
#pragma unroll
            for (int mt = 0; mt < 2; mt++)
                LDMX4(a[mt][0], a[mt][1], a[mt][2], a[mt][3], aA[mt] + ko);
#pragma unroll
            for (int nt = 0; nt < NT; nt++) {
                uint32_t b0, b1;
                LDMX2(b0, b1, aB[nt] + ko);
#pragma unroll
                for (int mt = 0; mt < 2; mt++)
                    MMA_F16(acc[mt][nt], a[mt], b0, b1);
            }
        }

        const int r0 = t * 64;
#pragma unroll
        for (int mt = 0; mt < 2; mt++) {
#pragma unroll
            for (int nt = 0; nt < NT; nt++) {
                int r1 = r0 + mbase + mt * 16 + g;
                int r2 = r1 + 8;
                int cc = nbase + nt * 8 + tg * 2;
                if (r1 < nrows)
                    *reinterpret_cast<__half2*>(C + (size_t)r1 * NCOL + cc) =
                        __floats2half2_rn(acc[mt][nt][0], acc[mt][nt][1]);
                if (r2 < nrows)
                    *reinterpret_cast<__half2*>(C + (size_t)r2 * NCOL + cc) =
                        __floats2half2_rn(acc[mt][nt][2], acc[mt][nt][3]);
            }
        }
        __syncthreads();
    }
}

// ---------------- agg1: mean + relu, fp16 in -> fp16 out ----------------------
__global__ void k_agg1(const __half* __restrict__ src, __half* __restrict__ dst) {
    const int gw = (blockIdx.x * blockDim.x + threadIdx.x) >> 5;
    if (gw >= NN) return;
    const int lane = threadIdx.x & 31;

    const int d = g_deg[gw];
    const int cnt = d < CAP ? d : CAP;
    const int* __restrict__ adj = g_adj + (size_t)gw * CAP;

    float acc[4] = {0.f, 0.f, 0.f, 0.f};
#pragma unroll 4
    for (int t = 0; t < cnt; t++) {
        int j = __ldg(&adj[t]);
        uint2 v = *reinterpret_cast<const uint2*>(src + (size_t)j * 128 + lane * 4);
        float2 f0 = __half22float2(*reinterpret_cast<__half2*>(&v.x));
        float2 f1 = __half22float2(*reinterpret_cast<__half2*>(&v.y));
        acc[0] += f0.x; acc[1] += f0.y; acc[2] += f1.x; acc[3] += f1.y;
    }

    const float inv = 1.0f / (float)d;
    float o0 = fmaxf(acc[0] * inv, 0.f), o1 = fmaxf(acc[1] * inv, 0.f);
    float o2 = fmaxf(acc[2] * inv, 0.f), o3 = fmaxf(acc[3] * inv, 0.f);

    __half2 h01 = __float22half2_rn(make_float2(o0, o1));
    __half2 h23 = __float22half2_rn(make_float2(o2, o3));
    *reinterpret_cast<uint2*>(dst + (size_t)gw * 128 + lane * 4) = make_uint2(
        *reinterpret_cast<uint32_t*>(&h01), *reinterpret_cast<uint32_t*>(&h23));
}

// ---------------- agg2: mean, fp16 in -> fp32 out -----------------------------
__global__ void k_agg2(const __half* __restrict__ src, float* __restrict__ dst) {
    const int gw = (blockIdx.x * blockDim.x + threadIdx.x) >> 5;
    if (gw >= NN) return;
    const int lane = threadIdx.x & 31;

    const int d = g_deg[gw];
    const int cnt = d < CAP ? d : CAP;
    const int* __restrict__ adj = g_adj + (size_t)gw * CAP;

    float acc0 = 0.f, acc1 = 0.f;
#pragma unroll 4
    for (int t = 0; t < cnt; t++) {
        int j = __ldg(&adj[t]);
        uint32_t v = *reinterpret_cast<const uint32_t*>(src + (size_t)j * 64 + lane * 2);
        float2 f = __half22float2(*reinterpret_cast<__half2*>(&v));
        acc0 += f.x; acc1 += f.y;
    }
    const float inv = 1.0f / (float)d;
    *reinterpret_cast<float2*>(dst + (size_t)gw * 64 + lane * 2) =
        make_float2(acc0 * inv, acc1 * inv);
}

// ---------------- launch --------------------------------------------------------
extern "C" void kernel_launch(void* const* d_in, const int* in_sizes, int n_in,
                              void* d_out, int out_size) {
    const float* x    = (const float*)d_in[0];
    const float* W1   = (const float*)d_in[1];
    const float* W2   = (const float*)d_in[2];
    const int*   erow = (const int*)d_in[3];
    const int*   ecol = (const int*)d_in[4];
    float* out = (float*)d_out;

    __half *h0, *h1, *h2, *w1, *w2;
    cudaGetSymbolAddress((void**)&h0, g_h0);
    cudaGetSymbolAddress((void**)&h1, g_h1);
    cudaGetSymbolAddress((void**)&h2, g_h2);
    cudaGetSymbolAddress((void**)&w1, g_w1);
    cudaGetSymbolAddress((void**)&w2, g_w2);

    const int SMEM = 2 * 64 * ROWB;   // 34816 (B + A), both GEMMs
    cudaFuncSetAttribute(k_gemm1, cudaFuncAttributeMaxDynamicSharedMemorySize, SMEM);
    cudaFuncSetAttribute(k_gemm2, cudaFuncAttributeMaxDynamicSharedMemorySize, SMEM);

    // fork a side stream so build_adj overlaps prep + gemm1
    cudaStream_t s2;
    cudaStreamCreateWithFlags(&s2, cudaStreamNonBlocking);
    cudaEvent_t evFork, evJoin;
    cudaEventCreateWithFlags(&evFork, cudaEventDisableTiming);
    cudaEventCreateWithFlags(&evJoin, cudaEventDisableTiming);

    k_prep_w1<<<(NN + 255) / 256, 256>>>(W1, w1);                                 // 1
    cudaEventRecord(evFork, 0);
    cudaStreamWaitEvent(s2, evFork, 0);
    k_build_adj<<<(EE / 4 + 255) / 256, 256, 0, s2>>>(erow, ecol);                // 2 (side)
    cudaEventRecord(evJoin, s2);

    k_prep_w2<<<(128 * 64 + 255) / 256, 256>>>(W2, w2);                           // 3
    k_gemm1<<<4 * NSM, 256, SMEM>>>(x, w1, h0, NN);                               // 4 (slot 4)

    cudaStreamWaitEvent(0, evJoin, 0);   // adjacency ready before agg1
    k_agg1<<<(NN * 32 + 255) / 256, 256>>>(h0, h1);                               // 5
    k_gemm2<<<3 * NSM, 256, SMEM>>>(h1, w2, h2, NN);                              // 6
    k_agg2<<<(NN * 32 + 255) / 256, 256>>>(h2, out);                              // 7

    cudaEventDestroy(evFork);
    cudaEventDestroy(evJoin);
    cudaStreamDestroy(s2);
}

// round 14
// speedup vs baseline: 1.2707x; 1.0470x over previous
#include <cuda_runtime.h>
#include <cuda_bf16.h>
#include <cuda_fp16.h>
#include <cstdint>

// Problem constants (fixed by the dataset)
#define NN   100000      // nodes
#define EE   1600000     // edges
#define CAP  128         // adjacency bucket capacity per node
#define NSM  152         // GB300 SM count

// ---------------- scratch (device globals; no allocation allowed) ----------
__device__ __half  g_h0[(size_t)NN * 128];   // x @ W1 (fp16)
__device__ __half  g_h1[(size_t)NN * 128];   // relu(agg h0) (fp16)
__device__ __half  g_h2[(size_t)NN * 64];    // h1 @ W2 (fp16)
__device__ int     g_deg[NN];
__device__ int     g_adj[(size_t)NN * CAP];
__device__ __half  g_w1[128 * 128];          // W1^T, fp16
__device__ __half  g_w2[64 * 128];           // W2^T, fp16

#define ROWB 272   // smem row pitch: 128 halves (256B) + 16B pad, ldmatrix conflict-free

// ---------------- prep 1: clear degrees + W1 transpose -> fp16 ---------------
__global__ void k_prep_w1(const float* __restrict__ W1, __half* __restrict__ w1) {
    int i = blockIdx.x * blockDim.x + threadIdx.x;
    if (i < NN) g_deg[i] = 0;
    if (i < 128 * 128) {
        int k = i / 128, n = i % 128;
        w1[n * 128 + k] = __float2half_rn(W1[i]);
    }
}

// ---------------- prep 2: W2 transpose -> fp16 --------------------------------
__global__ void k_prep_w2(const float* __restrict__ W2, __half* __restrict__ w2) {
    int i = blockIdx.x * blockDim.x + threadIdx.x;
    if (i < 128 * 64) {
        int k = i / 64, n = i % 64;
        w2[n * 128 + k] = __float2half_rn(W2[i]);
    }
}

// ---------------- adjacency build: 4 edges/thread ---------------------------
__global__ void k_build_adj(const int* __restrict__ erow,
                            const int* __restrict__ ecol) {
    int e0 = (blockIdx.x * blockDim.x + threadIdx.x) * 4;
    if (e0 >= EE) return;
    int4 r = *reinterpret_cast<const int4*>(erow + e0);
    int4 c = *reinterpret_cast<const int4*>(ecol + e0);
    int p0 = atomicAdd(&g_deg[r.x], 1);
    int p1 = atomicAdd(&g_deg[r.y], 1);
    int p2 = atomicAdd(&g_deg[r.z], 1);
    int p3 = atomicAdd(&g_deg[r.w], 1);
    if (p0 < CAP) g_adj[(size_t)r.x * CAP + p0] = c.x;
    if (p1 < CAP) g_adj[(size_t)r.y * CAP + p1] = c.y;
    if (p2 < CAP) g_adj[(size_t)r.z * CAP + p2] = c.z;
    if (p3 < CAP) g_adj[(size_t)r.w * CAP + p3] = c.w;
}

// ---------------- mma / ldmatrix helpers -------------------------------------
#define LDMX4(r0, r1, r2, r3, addr) \
    asm volatile("ldmatrix.sync.aligned.m8n8.x4.shared.b16 {%0,%1,%2,%3}, [%4];" \
                 : "=r"(r0), "=r"(r1), "=r"(r2), "=r"(r3) : "r"(addr))
#define LDMX2(r0, r1, addr) \
    asm volatile("ldmatrix.sync.aligned.m8n8.x2.shared.b16 {%0,%1}, [%2];" \
                 : "=r"(r0), "=r"(r1) : "r"(addr))
#define MMA_F16(acc, a, b0, b1) \
    asm volatile("mma.sync.aligned.m16n8k16.row.col.f32.f16.f16.f32 " \
                 "{%0,%1,%2,%3}, {%4,%5,%6,%7}, {%8,%9}, {%0,%1,%2,%3};" \
                 : "+f"(acc[0]), "+f"(acc[1]), "+f"(acc[2]), "+f"(acc[3]) \
                 : "r"(a[0]), "r"(a[1]), "r"(a[2]), "r"(a[3]), "r"(b0), "r"(b1))

// ---------------- GEMM1: fp32 A -> fp16 single-pass, FULL-N, reg-prefetch ----
// Output C[nrows,128](fp16). CTA tile 64 rows x 128 cols.
// 8 warps = 2(M) x 4(N); warp tile 32 x 32 (NT=4).
__global__ __launch_bounds__(256, 2)
void k_gemm1(const float* __restrict__ A, const __half* __restrict__ B,
             __half* __restrict__ C, int nrows) {
    constexpr int NC = 128;
    constexpr int WN = 32, NT = 4;
    constexpr int B_BYTES = NC * ROWB;

    extern __shared__ char smem[];
    char* sB = smem;
    char* sA = smem + B_BYTES;

    const int tid = threadIdx.x;
    const int lane = tid & 31;
    const int wid = tid >> 5;
    const int g = lane >> 2;
    const int tg = lane & 3;
    const int mbase = (wid & 1) * 32;
    const int nbase = (wid >> 1) * WN;

    // stage B once (128 rows x 16 uint4)
    for (int i = tid; i < NC * 16; i += 256) {
        int n = i >> 4, q = i & 15;
        *reinterpret_cast<uint4*>(sB + n * ROWB + q * 16) =
            reinterpret_cast<const uint4*>(B + n * 128)[q];
    }

    // ldmatrix base addresses
    const int rlm = lane & 7;
    const int qa = lane >> 3;
    uint32_t aA[2];
#pragma unroll
    for (int mt = 0; mt < 2; mt++) {
        int row = mbase + mt * 16 + (qa & 1) * 8 + rlm;
        int col = (qa >> 1) * 16;
        aA[mt] = (uint32_t)__cvta_generic_to_shared(sA) + row * ROWB + col;
    }
    const int lb = lane & 15;
    uint32_t aB[NT];
#pragma unroll
    for (int nt = 0; nt < NT; nt++) {
        int row = nbase + nt * 8 + (lb & 7);
        int col = ((lb >> 3) & 1) * 16;
        aB[nt] = (uint32_t)__cvta_generic_to_shared(sB) + row * ROWB + col;
    }

    const int ntiles = (nrows + 63) / 64;
    const int m0 = tid >> 5;    // rows m0, m0+8, ..., m0+56
    const int q0 = tid & 31;    // float4 column

    // prologue: load first tile into registers
    float4 v[8];
    {
        const int r0 = blockIdx.x * 64;
#pragma unroll
        for (int it = 0; it < 8; it++) {
            int gr = r0 + m0 + it * 8;
            v[it] = (gr < nrows && (int)blockIdx.x < ntiles)
                ? *reinterpret_cast<const float4*>(A + (size_t)gr * 128 + q0 * 4)
                : make_float4(0.f, 0.f, 0.f, 0.f);
        }
    }

    for (int t = blockIdx.x; t < ntiles; t += gridDim.x) {
        // convert + store registers -> smem (single fp16 plane)
#pragma unroll
        for (int it = 0; it < 8; it++) {
            int m = m0 + it * 8;
            __half2 h01 = __float22half2_rn(make_float2(v[it].x, v[it].y));
            __half2 h23 = __float22half2_rn(make_float2(v[it].z, v[it].w));
            *reinterpret_cast<uint2*>(sA + m * ROWB + q0 * 8) = make_uint2(
                *reinterpret_cast<uint32_t*>(&h01), *reinterpret_cast<uint32_t*>(&h23));
        }
        __syncthreads();

        // prefetch next tile — lands during the MMA phase
        const int tn = t + gridDim.x;
        if (tn < ntiles) {
            const int rn = tn * 64;
#pragma unroll
            for (int it = 0; it < 8; it++) {
                int gr = rn + m0 + it * 8;
                v[it] = (gr < nrows)
                    ? *reinterpret_cast<const float4*>(A + (size_t)gr * 128 + q0 * 4)
                    : make_float4(0.f, 0.f, 0.f, 0.f);
            }
        }

        float acc[2][NT][4];
#pragma unroll
        for (int mt = 0; mt < 2; mt++)
#pragma unroll
            for (int nt = 0; nt < NT; nt++)
#pragma unroll
                for (int j = 0; j < 4; j++) acc[mt][nt][j] = 0.0f;

#pragma unroll
        for (int ks = 0; ks < 8; ks++) {
            const uint32_t ko = ks * 32;
            uint32_t a[2][4];
#pragma unroll
            for (int mt = 0; mt < 2; mt++)
                LDMX4(a[mt][0], a[mt][1], a[mt][2], a[mt][3], aA[mt] + ko);
#pragma unroll
            for (int nt = 0; nt < NT; nt++) {
                uint32_t b0, b1;
                LDMX2(b0, b1, aB[nt] + ko);
#pragma unroll
                for (int mt = 0; mt < 2; mt++)
                    MMA_F16(acc[mt][nt], a[mt], b0, b1);
            }
        }

        const int r0 = t * 64;
#pragma unroll
        for (int mt = 0; mt < 2; mt++) {
#pragma unroll
            for (int nt = 0; nt < NT; nt++) {
                int r1 = r0 + mbase + mt * 16 + g;
                int r2 = r1 + 8;
                int cc = nbase + nt * 8 + tg * 2;
                if (r1 < nrows)
                    *reinterpret_cast<__half2*>(C + (size_t)r1 * 128 + cc) =
                        __floats2half2_rn(acc[mt][nt][0], acc[mt][nt][1]);
                if (r2 < nrows)
                    *reinterpret_cast<__half2*>(C + (size_t)r2 * 128 + cc) =
                        __floats2half2_rn(acc[mt][nt][2], acc[mt][nt][3]);
            }
        }
        __syncthreads();
    }
}

// ---------------- GEMM2: single fp16 A plane, single-pass (unchanged) --------
__global__ __launch_bounds__(256, 3)
void k_gemm2(const __half* __restrict__ A, const __half* __restrict__ B,
             __half* __restrict__ C, int nrows) {
    constexpr int NCOL = 64;
    constexpr int WN = 16, NT = 2;
    constexpr int B_BYTES = NCOL * ROWB;

    extern __shared__ char smem[];
    char* sB = smem;
    char* sA = smem + B_BYTES;

    const int tid = threadIdx.x;
    const int lane = tid & 31;
    const int wid = tid >> 5;
    const int g = lane >> 2;
    const int tg = lane & 3;
    const int mbase = (wid & 1) * 32;
    const int nbase = (wid >> 1) * WN;

    for (int i = tid; i < NCOL * 16; i += 256) {
        int n = i >> 4, q = i & 15;
        *reinterpret_cast<uint4*>(sB + n * ROWB + q * 16) =
            reinterpret_cast<const uint4*>(B + n * 128)[q];
    }

    const int rlm = lane & 7;
    const int qa = lane >> 3;
    uint32_t aA[2];
#pragma unroll
    for (int mt = 0; mt < 2; mt++) {
        int row = mbase + mt * 16 + (qa & 1) * 8 + rlm;
        int col = (qa >> 1) * 16;
        aA[mt] = (uint32_t)__cvta_generic_to_shared(sA) + row * ROWB + col;
    }
    const int lb = lane & 15;
    uint32_t aB[NT];
#pragma unroll
    for (int nt = 0; nt < NT; nt++) {
        int row = nbase + nt * 8 + (lb & 7);
        int col = ((lb >> 3) & 1) * 16;
        aB[nt] = (uint32_t)__cvta_generic_to_shared(sB) + row * ROWB + col;
    }

    const int ntiles = (nrows + 63) / 64;
    const int m0 = tid >> 4;
    const int q0 = tid & 15;

    uint4 v[4];
    {
        const int r0 = blockIdx.x * 64;
#pragma unroll
        for (int it = 0; it < 4; it++) {
            int gr = r0 + m0 + it * 16;
            v[it] = (gr < nrows && (int)blockIdx.x < ntiles)
                ? reinterpret_cast<const uint4*>(A + (size_t)gr * 128)[q0]
                : make_uint4(0u, 0u, 0u, 0u);
        }
    }

    for (int t = blockIdx.x; t < ntiles; t += gridDim.x) {
#pragma unroll
        for (int it = 0; it < 4; it++)
            *reinterpret_cast<uint4*>(sA + (m0 + it * 16) * ROWB + q0 * 16) = v[it];
        __syncthreads();

        const int tn = t + gridDim.x;
        if (tn < ntiles) {
            const int rn = tn * 64;
#pragma unroll
            for (int it = 0; it < 4; it++) {
                int gr = rn + m0 + it * 16;
                v[it] = (gr < nrows)
                    ? reinterpret_cast<const uint4*>(A + (size_t)gr * 128)[q0]
                    : make_uint4(0u, 0u, 0u, 0u);
            }
        }

        float acc[2][NT][4];
#pragma unroll
        for (int mt = 0; mt < 2; mt++)
#pragma unroll
            for (int nt = 0; nt < NT; nt++)
#pragma unroll
                for (int j = 0; j < 4; j++) acc[mt][nt][j] = 0.0f;

#pragma unroll
        for (int ks = 0; ks < 8; ks++) {
            const uint32_t ko = ks * 32;
            uint32_t a[2][4];
#pragma unroll
            for (int mt = 0; mt < 2; mt++)
                LDMX4(a[mt][0], a[mt][1], a[mt][2], a[mt][3], aA[mt] + ko);
#pragma unroll
            for (int nt = 0; nt < NT; nt++) {
                uint32_t b0, b1;
                LDMX2(b0, b1, aB[nt] + ko);
#pragma unroll
                for (int mt = 0; mt < 2; mt++)
                    MMA_F16(acc[mt][nt], a[mt], b0, b1);
            }
        }

        const int r0 = t * 64;
#pragma unroll
        for (int mt = 0; mt < 2; mt++) {
#pragma unroll
            for (int nt = 0; nt < NT; nt++) {
                int r1 = r0 + mbase + mt * 16 + g;
                int r2 = r1 + 8;
                int cc = nbase + nt * 8 + tg * 2;
                if (r1 < nrows)
                    *reinterpret_cast<__half2*>(C + (size_t)r1 * NCOL + cc) =
                        __floats2half2_rn(acc[mt][nt][0], acc[mt][nt][1]);
                if (r2 < nrows)
                    *reinterpret_cast<__half2*>(C + (size_t)r2 * NCOL + cc) =
                        __floats2half2_rn(acc[mt][nt][2], acc[mt][nt][3]);
            }
        }
        __syncthreads();
    }
}

// ---------------- agg1: mean + relu, fp16 in -> fp16 out ----------------------
__global__ void k_agg1(const __half* __restrict__ src, __half* __restrict__ dst) {
    const int gw = (blockIdx.x * blockDim.x + threadIdx.x) >> 5;
    if (gw >= NN) return;
    const int lane = threadIdx.x & 31;

    const int d = g_deg[gw];
    const int cnt = d < CAP ? d : CAP;
    const int* __restrict__ adj = g_adj + (size_t)gw * CAP;

    float acc[4] = {0.f, 0.f, 0.f, 0.f};
#pragma unroll 4
    for (int t = 0; t < cnt; t++) {
        int j = __ldg(&adj[t]);
        uint2 v = *reinterpret_cast<const uint2*>(src + (size_t)j * 128 + lane * 4);
        float2 f0 = __half22float2(*reinterpret_cast<__half2*>(&v.x));
        float2 f1 = __half22float2(*reinterpret_cast<__half2*>(&v.y));
        acc[0] += f0.x; acc[1] += f0.y; acc[2] += f1.x; acc[3] += f1.y;
    }

    const float inv = 1.0f / (float)d;
    float o0 = fmaxf(acc[0] * inv, 0.f), o1 = fmaxf(acc[1] * inv, 0.f);
    float o2 = fmaxf(acc[2] * inv, 0.f), o3 = fmaxf(acc[3] * inv, 0.f);

    __half2 h01 = __float22half2_rn(make_float2(o0, o1));
    __half2 h23 = __float22half2_rn(make_float2(o2, o3));
    *reinterpret_cast<uint2*>(dst + (size_t)gw * 128 + lane * 4) = make_uint2(
        *reinterpret_cast<uint32_t*>(&h01), *reinterpret_cast<uint32_t*>(&h23));
}

// ---------------- agg2: mean, fp16 in -> fp32 out -----------------------------
__global__ void k_agg2(const __half* __restrict__ src, float* __restrict__ dst) {
    const int gw = (blockIdx.x * blockDim.x + threadIdx.x) >> 5;
    if (gw >= NN) return;
    const int lane = threadIdx.x & 31;

    const int d = g_deg[gw];
    const int cnt = d < CAP ? d : CAP;
    const int* __restrict__ adj = g_adj + (size_t)gw * CAP;

    float acc0 = 0.f, acc1 = 0.f;
#pragma unroll 4
    for (int t = 0; t < cnt; t++) {
        int j = __ldg(&adj[t]);
        uint32_t v = *reinterpret_cast<const uint32_t*>(src + (size_t)j * 64 + lane * 2);
        float2 f = __half22float2(*reinterpret_cast<__half2*>(&v));
        acc0 += f.x; acc1 += f.y;
    }
    const float inv = 1.0f / (float)d;
    *reinterpret_cast<float2*>(dst + (size_t)gw * 64 + lane * 2) =
        make_float2(acc0 * inv, acc1 * inv);
}

// ---------------- launch --------------------------------------------------------
extern "C" void kernel_launch(void* const* d_in, const int* in_sizes, int n_in,
                              void* d_out, int out_size) {
    const float* x    = (const float*)d_in[0];
    const float* W1   = (const float*)d_in[1];
    const float* W2   = (const float*)d_in[2];
    const int*   erow = (const int*)d_in[3];
    const int*   ecol = (const int*)d_in[4];
    float* out = (float*)d_out;

    __half *h0, *h1, *h2, *w1, *w2;
    cudaGetSymbolAddress((void**)&h0, g_h0);
    cudaGetSymbolAddress((void**)&h1, g_h1);
    cudaGetSymbolAddress((void**)&h2, g_h2);
    cudaGetSymbolAddress((void**)&w1, g_w1);
    cudaGetSymbolAddress((void**)&w2, g_w2);

    const int SMEM1 = 128 * ROWB + 64 * ROWB;  // 52224 (B full + A tile)
    const int SMEM2 = 2 * 64 * ROWB;           // 34816
    cudaFuncSetAttribute(k_gemm1, cudaFuncAttributeMaxDynamicSharedMemorySize, SMEM1);
    cudaFuncSetAttribute(k_gemm2, cudaFuncAttributeMaxDynamicSharedMemorySize, SMEM2);

    // fork a side stream so build_adj overlaps prep + gemm1
    cudaStream_t s2;
    cudaStreamCreateWithFlags(&s2, cudaStreamNonBlocking);
    cudaEvent_t evFork, evJoin;
    cudaEventCreateWithFlags(&evFork, cudaEventDisableTiming);
    cudaEventCreateWithFlags(&evJoin, cudaEventDisableTiming);

    k_prep_w1<<<(NN + 255) / 256, 256>>>(W1, w1);                                 // 1
    cudaEventRecord(evFork, 0);
    cudaStreamWaitEvent(s2, evFork, 0);
    k_build_adj<<<(EE / 4 + 255) / 256, 256, 0, s2>>>(erow, ecol);                // 2 (side)
    cudaEventRecord(evJoin, s2);

    k_prep_w2<<<(128 * 64 + 255) / 256, 256>>>(W2, w2);                           // 3
    k_gemm1<<<2 * NSM, 256, SMEM1>>>(x, w1, h0, NN);                              // 4 (slot 4)

    cudaStreamWaitEvent(0, evJoin, 0);   // adjacency ready before agg1
    k_agg1<<<(NN * 32 + 255) / 256, 256>>>(h0, h1);                               // 5
    k_gemm2<<<3 * NSM, 256, SMEM2>>>(h1, w2, h2, NN);                             // 6
    k_agg2<<<(NN * 32 + 255) / 256, 256>>>(h2, out);                              // 7

    cudaEventDestroy(evFork);
    cudaEventDestroy(evJoin);
    cudaStreamDestroy(s2);
}